// round 5
// baseline (speedup 1.0000x reference)
#include <cuda_runtime.h>
#include <cuda_bf16.h>
#include <cuda_fp16.h>
#include <mma.h>
#include <cstdint>
#include <math.h>

using namespace nvcuda;

// Block: B=1, T=4096, C=1024, H=16, hs=64
#define SEQ 4096
#define EMB 1024
#define NHEAD 16
#define HS 64
#define C3 3072
#define CFC 4096

typedef __nv_bfloat16 bf16;

// ---------------- device scratch (no allocations allowed) ----------------
__device__ bf16 g_h_hi[SEQ * EMB], g_h_lo[SEQ * EMB];        // LN out (split)
__device__ float g_qkv[SEQ * C3];                            // qkv fp32
__device__ bf16 g_attn_hi[SEQ * EMB], g_attn_lo[SEQ * EMB];  // attention out (split)
__device__ float g_x1[SEQ * EMB];                            // x + attn_proj
__device__ float g_fc32[SEQ * CFC];                          // fc pre-gelu fp32
__device__ bf16 g_fc_hi[SEQ * CFC], g_fc_lo[SEQ * CFC];      // gelu(fc) (split)
// transposed + split weights: Wt[n][k]
__device__ bf16 g_wqkv_hi[C3 * EMB], g_wqkv_lo[C3 * EMB];
__device__ bf16 g_wproj_hi[EMB * EMB], g_wproj_lo[EMB * EMB];
__device__ bf16 g_wfc_hi[CFC * EMB], g_wfc_lo[CFC * EMB];
__device__ bf16 g_wmlp_hi[EMB * CFC], g_wmlp_lo[EMB * CFC];

__device__ __forceinline__ void split_bf16(float v, bf16& hi, bf16& lo) {
    hi = __float2bfloat16(v);
    lo = __float2bfloat16(v - __bfloat162float(hi));
}
__device__ __forceinline__ float gelu_exact(float v) {
    return 0.5f * v * (1.0f + erff(v * 0.70710678118654752440f));
}

// ---- cp.async helpers ----
__device__ __forceinline__ uint32_t smem_u32(const void* p) {
    uint32_t a;
    asm("{ .reg .u64 t; cvta.to.shared.u64 t, %1; cvt.u32.u64 %0, t; }" : "=r"(a) : "l"(p));
    return a;
}
__device__ __forceinline__ void cp16(void* sp, const void* gp) {
    asm volatile("cp.async.cg.shared.global [%0], [%1], 16;" :: "r"(smem_u32(sp)), "l"(gp));
}
__device__ __forceinline__ void cp_commit() {
    asm volatile("cp.async.commit_group;" ::: "memory");
}
__device__ __forceinline__ void cp_wait0() {
    asm volatile("cp.async.wait_group 0;" ::: "memory");
}
__device__ __forceinline__ void cp_wait1() {
    asm volatile("cp.async.wait_group 1;" ::: "memory");
}

// ---------------- LayerNorm -> split bf16 ----------------
__global__ void ln_kernel(const float* __restrict__ x, const float* __restrict__ w,
                          bf16* __restrict__ out_hi, bf16* __restrict__ out_lo) {
    const int row = blockIdx.x;
    const int tid = threadIdx.x;  // 256, 4 floats each
    const float4 v = reinterpret_cast<const float4*>(x + (size_t)row * EMB)[tid];

    float s = v.x + v.y + v.z + v.w;
    float q = v.x * v.x + v.y * v.y + v.z * v.z + v.w * v.w;
    #pragma unroll
    for (int off = 16; off > 0; off >>= 1) {
        s += __shfl_xor_sync(0xffffffffu, s, off);
        q += __shfl_xor_sync(0xffffffffu, q, off);
    }
    __shared__ float ws[8], wq[8], s_mean, s_rstd;
    const int wid = tid >> 5, lane = tid & 31;
    if (lane == 0) { ws[wid] = s; wq[wid] = q; }
    __syncthreads();
    if (tid == 0) {
        float S = 0.f, Q = 0.f;
        #pragma unroll
        for (int i = 0; i < 8; i++) { S += ws[i]; Q += wq[i]; }
        float mean = S * (1.0f / EMB);
        float var = Q * (1.0f / EMB) - mean * mean;
        s_mean = mean;
        s_rstd = rsqrtf(var + 1e-5f);
    }
    __syncthreads();
    const float mean = s_mean, rstd = s_rstd;
    const float4 g = reinterpret_cast<const float4*>(w)[tid];
    float o[4] = {(v.x - mean) * rstd * g.x, (v.y - mean) * rstd * g.y,
                  (v.z - mean) * rstd * g.z, (v.w - mean) * rstd * g.w};
    const size_t base = (size_t)row * EMB + tid * 4;
    #pragma unroll
    for (int i = 0; i < 4; i++) {
        bf16 hi, lo;
        split_bf16(o[i], hi, lo);
        out_hi[base + i] = hi;
        out_lo[base + i] = lo;
    }
}

// ---------------- weight transpose + split: W[K,N] fp32 -> Wt_hi/lo[N,K] bf16 ----------------
__global__ __launch_bounds__(256) void wt_split_kernel(const float* __restrict__ W,
                                                       bf16* __restrict__ th,
                                                       bf16* __restrict__ tl,
                                                       int K, int N) {
    __shared__ float tile[32][33];
    const int bn = blockIdx.x * 32;
    const int bk = blockIdx.y * 32;
    const int tx = threadIdx.x & 31, ty = threadIdx.x >> 5;
    #pragma unroll
    for (int r = ty; r < 32; r += 8)
        tile[r][tx] = W[(size_t)(bk + r) * N + bn + tx];
    __syncthreads();
    #pragma unroll
    for (int r = ty; r < 32; r += 8) {
        const float v = tile[tx][r];  // = W[bk+tx][bn+r]
        bf16 hi, lo;
        split_bf16(v, hi, lo);
        const size_t o = (size_t)(bn + r) * K + bk + tx;
        th[o] = hi;
        tl[o] = lo;
    }
}

// ---------------- gelu + split (elementwise) ----------------
__global__ __launch_bounds__(256) void gelu_split_kernel(const float* __restrict__ in,
                                                         bf16* __restrict__ oh,
                                                         bf16* __restrict__ ol) {
    const size_t i = ((size_t)blockIdx.x * 256 + threadIdx.x) * 4;
    const float4 v = *reinterpret_cast<const float4*>(in + i);
    float g[4] = {gelu_exact(v.x), gelu_exact(v.y), gelu_exact(v.z), gelu_exact(v.w)};
    #pragma unroll
    for (int j = 0; j < 4; j++) {
        bf16 hi, lo;
        split_bf16(g[j], hi, lo);
        oh[i + j] = hi;
        ol[i + j] = lo;
    }
}

// ---------------- WMMA GEMM: 128x256 CTA tile, 64x64 warp tile, KC=32, bf16x3 ----------------
// C[M,N] = A[M,K] @ Wt[N,K]^T. EPI: 0 = plain fp32 C, 1 = C = R + acc
#define KC 32
#define SPAD 40                      // smem row stride in bf16 elems (80 B, 16B-multiple)
#define A_ELEMS (128 * SPAD)
#define B_ELEMS (256 * SPAD)
#define STAGE_ELEMS (2 * A_ELEMS + 2 * B_ELEMS)

template <int EPI>
__global__ __launch_bounds__(256, 1) void mma_gemm(
    const bf16* __restrict__ Ah, const bf16* __restrict__ Al,
    const bf16* __restrict__ Bh, const bf16* __restrict__ Bl,
    const float* __restrict__ R, float* __restrict__ C,
    int M, int N, int K) {
    extern __shared__ char smraw[];
    bf16* sm = reinterpret_cast<bf16*>(smraw);

    const int tid = threadIdx.x;
    const int wid = tid >> 5;
    const int wm = wid & 1;        // 2 warps in M  (64 rows each)
    const int wn = wid >> 1;       // 4 warps in N  (64 cols each)
    const int bm = blockIdx.y * 128, bn = blockIdx.x * 256;

    wmma::fragment<wmma::accumulator, 16, 16, 16, float> acc[4][4];
    if (EPI == 1) {
        #pragma unroll
        for (int i = 0; i < 4; i++)
            #pragma unroll
            for (int j = 0; j < 4; j++)
                wmma::load_matrix_sync(
                    acc[i][j],
                    R + (size_t)(bm + wm * 64 + i * 16) * N + bn + wn * 64 + j * 16,
                    N, wmma::mem_row_major);
    } else {
        #pragma unroll
        for (int i = 0; i < 4; i++)
            #pragma unroll
            for (int j = 0; j < 4; j++)
                wmma::fill_fragment(acc[i][j], 0.0f);
    }

    const int NC = K / KC;

    // stage loader: A 128x32 hi/lo (512 cp16 x2), B 256x32 hi/lo (1024 cp16 x2) = 12/thread
    auto load_stage = [&](int buf, int k0) {
        bf16* st = sm + buf * STAGE_ELEMS;
        bf16* dAh = st;
        bf16* dAl = st + A_ELEMS;
        bf16* dBh = st + 2 * A_ELEMS;
        bf16* dBl = st + 2 * A_ELEMS + B_ELEMS;
        #pragma unroll
        for (int o = 0; o < 2; o++) {
            const int idx = tid + o * 256;        // 0..511
            const int row = idx >> 2, seg = idx & 3;
            const int soff = row * SPAD + seg * 8;
            const size_t ga = (size_t)(bm + row) * K + k0 + seg * 8;
            cp16(dAh + soff, Ah + ga);
            cp16(dAl + soff, Al + ga);
        }
        #pragma unroll
        for (int o = 0; o < 4; o++) {
            const int idx = tid + o * 256;        // 0..1023
            const int row = idx >> 2, seg = idx & 3;
            const int soff = row * SPAD + seg * 8;
            const size_t gb = (size_t)(bn + row) * K + k0 + seg * 8;
            cp16(dBh + soff, Bh + gb);
            cp16(dBl + soff, Bl + gb);
        }
    };

    load_stage(0, 0);
    cp_commit();

    for (int c = 0; c < NC; c++) {
        if (c + 1 < NC) {
            load_stage((c + 1) & 1, (c + 1) * KC);
            cp_commit();
            cp_wait1();
        } else {
            cp_wait0();
        }
        __syncthreads();

        bf16* st = sm + (c & 1) * STAGE_ELEMS;
        bf16* sAh = st;
        bf16* sAl = st + A_ELEMS;
        bf16* sBh = st + 2 * A_ELEMS;
        bf16* sBl = st + 2 * A_ELEMS + B_ELEMS;

        #pragma unroll
        for (int kk = 0; kk < KC / 16; kk++) {
            wmma::fragment<wmma::matrix_b, 16, 16, 16, bf16, wmma::col_major> b_hi[4], b_lo[4];
            #pragma unroll
            for (int j = 0; j < 4; j++) {
                const int nb = (wn * 64 + j * 16) * SPAD + kk * 16;
                wmma::load_matrix_sync(b_hi[j], sBh + nb, SPAD);
                wmma::load_matrix_sync(b_lo[j], sBl + nb, SPAD);
            }
            #pragma unroll
            for (int i = 0; i < 4; i++) {
                wmma::fragment<wmma::matrix_a, 16, 16, 16, bf16, wmma::row_major> a_hi, a_lo;
                const int ab = (wm * 64 + i * 16) * SPAD + kk * 16;
                wmma::load_matrix_sync(a_hi, sAh + ab, SPAD);
                wmma::load_matrix_sync(a_lo, sAl + ab, SPAD);
                #pragma unroll
                for (int j = 0; j < 4; j++) {
                    wmma::mma_sync(acc[i][j], a_hi, b_hi[j], acc[i][j]);
                    wmma::mma_sync(acc[i][j], a_hi, b_lo[j], acc[i][j]);
                    wmma::mma_sync(acc[i][j], a_lo, b_hi[j], acc[i][j]);
                }
            }
        }
        __syncthreads();
    }

    #pragma unroll
    for (int i = 0; i < 4; i++)
        #pragma unroll
        for (int j = 0; j < 4; j++)
            wmma::store_matrix_sync(
                C + (size_t)(bm + wm * 64 + i * 16) * N + bn + wn * 64 + j * 16,
                acc[i][j], N, wmma::mem_row_major);
}

// ---------------- Tensor-core flash attention (causal), 64q x 64k, hs=64 ----------------
// S = Qh @ (Kh + Kl)^T (fp16 2-pass), softmax fp32 in smem, O += P @ Vh (fp16 1-pass)
#define QPAD 72

__global__ __launch_bounds__(256, 2) void flash_tc(
    const float* __restrict__ qkv, bf16* __restrict__ out_hi, bf16* __restrict__ out_lo) {
    extern __shared__ char smraw[];
    __half* Qh = reinterpret_cast<__half*>(smraw);   // 64x72
    __half* Kh = Qh + 64 * QPAD;
    __half* Kl = Kh + 64 * QPAD;
    __half* Vh = Kl + 64 * QPAD;
    __half* Pm = Vh + 64 * QPAD;
    float* Sf = reinterpret_cast<float*>(Pm + 64 * QPAD);  // 64x72 fp32
    float* Of = Sf + 64 * QPAD;                            // 64x72 fp32

    const int tid = threadIdx.x;
    const int wid = tid >> 5;
    const int wm = wid >> 2;   // 2 warps in M (32 rows each)
    const int wn = wid & 3;    // 4 warps in N (16 cols each)
    const int qb = gridDim.x - 1 - blockIdx.x;   // heavy tiles first
    const int hd = blockIdx.y;

    // load Q tile (fp16 hi only), init O = 0
    for (int i = tid; i < 4096; i += 256) {
        const int r = i >> 6, c = i & 63;
        const float q = qkv[(size_t)(qb * 64 + r) * C3 + hd * HS + c];
        Qh[r * QPAD + c] = __float2half(q);
        Of[r * QPAD + c] = 0.f;
    }

    float mi = -1e30f, li = 0.f;
    const int row = tid >> 2, quad = tid & 3;

    for (int kt = 0; kt <= qb; kt++) {
        __syncthreads();
        // load + split K; V hi only
        for (int i = tid; i < 4096; i += 256) {
            const int r = i >> 6, c = i & 63;
            const size_t base = (size_t)(kt * 64 + r) * C3 + hd * HS + c;
            const float k = qkv[base + EMB];
            const __half kh = __float2half(k);
            Kh[r * QPAD + c] = kh;
            Kl[r * QPAD + c] = __float2half(k - __half2float(kh));
            Vh[r * QPAD + c] = __float2half(qkv[base + 2 * EMB]);
        }
        __syncthreads();

        // S = Qh @ K^T (K split 2-pass)
        {
            wmma::fragment<wmma::accumulator, 16, 16, 16, float> sa[2];
            #pragma unroll
            for (int i = 0; i < 2; i++) wmma::fill_fragment(sa[i], 0.0f);
            #pragma unroll
            for (int kk = 0; kk < 4; kk++) {
                wmma::fragment<wmma::matrix_b, 16, 16, 16, __half, wmma::col_major> bh, bl;
                const int nb = (wn * 16) * QPAD + kk * 16;
                wmma::load_matrix_sync(bh, Kh + nb, QPAD);
                wmma::load_matrix_sync(bl, Kl + nb, QPAD);
                #pragma unroll
                for (int i = 0; i < 2; i++) {
                    wmma::fragment<wmma::matrix_a, 16, 16, 16, __half, wmma::row_major> a;
                    wmma::load_matrix_sync(a, Qh + (wm * 32 + i * 16) * QPAD + kk * 16, QPAD);
                    wmma::mma_sync(sa[i], a, bh, sa[i]);
                    wmma::mma_sync(sa[i], a, bl, sa[i]);
                }
            }
            #pragma unroll
            for (int i = 0; i < 2; i++)
                wmma::store_matrix_sync(Sf + (wm * 32 + i * 16) * QPAD + wn * 16,
                                        sa[i], QPAD, wmma::mem_row_major);
        }
        __syncthreads();

        // online softmax: thread -> (row, quad of 16 cols)
        {
            const bool diag = (kt == qb);
            float s[16];
            float mx = -1e30f;
            #pragma unroll
            for (int j = 0; j < 16; j++) {
                float v = Sf[row * QPAD + quad * 16 + j] * 0.125f;
                if (diag && (quad * 16 + j) > row) v = -1e30f;
                s[j] = v;
                mx = fmaxf(mx, v);
            }
            mx = fmaxf(mx, __shfl_xor_sync(0xffffffffu, mx, 1));
            mx = fmaxf(mx, __shfl_xor_sync(0xffffffffu, mx, 2));
            const float mn = fmaxf(mi, mx);
            const float alpha = __expf(mi - mn);
            float rs = 0.f;
            #pragma unroll
            for (int j = 0; j < 16; j++) {
                const float p = __expf(s[j] - mn);
                Pm[row * QPAD + quad * 16 + j] = __float2half(p);
                rs += p;
            }
            rs += __shfl_xor_sync(0xffffffffu, rs, 1);
            rs += __shfl_xor_sync(0xffffffffu, rs, 2);
            li = li * alpha + rs;
            mi = mn;
            #pragma unroll
            for (int j = 0; j < 16; j++)
                Of[row * QPAD + quad * 16 + j] *= alpha;
        }
        __syncthreads();

        // O += P @ Vh
        {
            wmma::fragment<wmma::accumulator, 16, 16, 16, float> oa[2];
            #pragma unroll
            for (int i = 0; i < 2; i++)
                wmma::load_matrix_sync(oa[i], Of + (wm * 32 + i * 16) * QPAD + wn * 16,
                                       QPAD, wmma::mem_row_major);
            #pragma unroll
            for (int kk = 0; kk < 4; kk++) {
                wmma::fragment<wmma::matrix_b, 16, 16, 16, __half, wmma::row_major> bh;
                wmma::load_matrix_sync(bh, Vh + (kk * 16) * QPAD + wn * 16, QPAD);
                #pragma unroll
                for (int i = 0; i < 2; i++) {
                    wmma::fragment<wmma::matrix_a, 16, 16, 16, __half, wmma::row_major> a;
                    wmma::load_matrix_sync(a, Pm + (wm * 32 + i * 16) * QPAD + kk * 16, QPAD);
                    wmma::mma_sync(oa[i], a, bh, oa[i]);
                }
            }
            #pragma unroll
            for (int i = 0; i < 2; i++)
                wmma::store_matrix_sync(Of + (wm * 32 + i * 16) * QPAD + wn * 16,
                                        oa[i], QPAD, wmma::mem_row_major);
        }
    }
    __syncthreads();

    // finalize: attn = O / li, split bf16
    {
        const float inv = 1.0f / li;
        #pragma unroll
        for (int j = 0; j < 16; j++) {
            const float v = Of[row * QPAD + quad * 16 + j] * inv;
            bf16 hi, lo;
            split_bf16(v, hi, lo);
            const size_t o = (size_t)(qb * 64 + row) * EMB + hd * HS + quad * 16 + j;
            out_hi[o] = hi;
            out_lo[o] = lo;
        }
    }
}

// ---------------- launch ----------------
extern "C" void kernel_launch(void* const* d_in, const int* in_sizes, int n_in,
                              void* d_out, int out_size) {
    const float* x           = (const float*)d_in[0];
    const float* w_qkv       = (const float*)d_in[1];
    const float* w_attn_proj = (const float*)d_in[2];
    const float* w_fc        = (const float*)d_in[3];
    const float* w_mlp_proj  = (const float*)d_in[4];
    const float* ln1_w       = (const float*)d_in[5];
    const float* ln2_w       = (const float*)d_in[6];
    float* out = (float*)d_out;

    bf16 *p_h_hi, *p_h_lo, *p_attn_hi, *p_attn_lo, *p_fc_hi, *p_fc_lo;
    bf16 *p_wqkv_hi, *p_wqkv_lo, *p_wproj_hi, *p_wproj_lo;
    bf16 *p_wfc_hi, *p_wfc_lo, *p_wmlp_hi, *p_wmlp_lo;
    float *p_qkv, *p_x1, *p_fc32;
    cudaGetSymbolAddress((void**)&p_h_hi, g_h_hi);
    cudaGetSymbolAddress((void**)&p_h_lo, g_h_lo);
    cudaGetSymbolAddress((void**)&p_qkv, g_qkv);
    cudaGetSymbolAddress((void**)&p_attn_hi, g_attn_hi);
    cudaGetSymbolAddress((void**)&p_attn_lo, g_attn_lo);
    cudaGetSymbolAddress((void**)&p_x1, g_x1);
    cudaGetSymbolAddress((void**)&p_fc32, g_fc32);
    cudaGetSymbolAddress((void**)&p_fc_hi, g_fc_hi);
    cudaGetSymbolAddress((void**)&p_fc_lo, g_fc_lo);
    cudaGetSymbolAddress((void**)&p_wqkv_hi, g_wqkv_hi);
    cudaGetSymbolAddress((void**)&p_wqkv_lo, g_wqkv_lo);
    cudaGetSymbolAddress((void**)&p_wproj_hi, g_wproj_hi);
    cudaGetSymbolAddress((void**)&p_wproj_lo, g_wproj_lo);
    cudaGetSymbolAddress((void**)&p_wfc_hi, g_wfc_hi);
    cudaGetSymbolAddress((void**)&p_wfc_lo, g_wfc_lo);
    cudaGetSymbolAddress((void**)&p_wmlp_hi, g_wmlp_hi);
    cudaGetSymbolAddress((void**)&p_wmlp_lo, g_wmlp_lo);

    const int gemm_smem = 2 * STAGE_ELEMS * (int)sizeof(bf16);   // 122,880 B
    cudaFuncSetAttribute(mma_gemm<0>, cudaFuncAttributeMaxDynamicSharedMemorySize, gemm_smem);
    cudaFuncSetAttribute(mma_gemm<1>, cudaFuncAttributeMaxDynamicSharedMemorySize, gemm_smem);
    const int flash_smem = 64 * QPAD * (5 * (int)sizeof(__half) + 2 * (int)sizeof(float));  // 82,944 B
    cudaFuncSetAttribute(flash_tc, cudaFuncAttributeMaxDynamicSharedMemorySize, flash_smem);

    // 0. weight transpose + split
    wt_split_kernel<<<dim3(C3 / 32, EMB / 32), 256>>>(w_qkv, p_wqkv_hi, p_wqkv_lo, EMB, C3);
    wt_split_kernel<<<dim3(EMB / 32, EMB / 32), 256>>>(w_attn_proj, p_wproj_hi, p_wproj_lo, EMB, EMB);
    wt_split_kernel<<<dim3(CFC / 32, EMB / 32), 256>>>(w_fc, p_wfc_hi, p_wfc_lo, EMB, CFC);
    wt_split_kernel<<<dim3(EMB / 32, CFC / 32), 256>>>(w_mlp_proj, p_wmlp_hi, p_wmlp_lo, CFC, EMB);

    // 1. h = LN(x, ln1)
    ln_kernel<<<SEQ, 256>>>(x, ln1_w, p_h_hi, p_h_lo);
    // 2. qkv = h @ w_qkv
    mma_gemm<0><<<dim3(C3 / 256, SEQ / 128), 256, gemm_smem>>>(
        p_h_hi, p_h_lo, p_wqkv_hi, p_wqkv_lo, nullptr, p_qkv, SEQ, C3, EMB);
    // 3. attention (tensor core)
    flash_tc<<<dim3(SEQ / 64, NHEAD), 256, flash_smem>>>(p_qkv, p_attn_hi, p_attn_lo);
    // 4. x1 = x + attn @ w_attn_proj
    mma_gemm<1><<<dim3(EMB / 256, SEQ / 128), 256, gemm_smem>>>(
        p_attn_hi, p_attn_lo, p_wproj_hi, p_wproj_lo, x, p_x1, SEQ, EMB, EMB);
    // 5. h = LN(x1, ln2)
    ln_kernel<<<SEQ, 256>>>(p_x1, ln2_w, p_h_hi, p_h_lo);
    // 6. fc32 = h @ w_fc, then gelu+split
    mma_gemm<0><<<dim3(CFC / 256, SEQ / 128), 256, gemm_smem>>>(
        p_h_hi, p_h_lo, p_wfc_hi, p_wfc_lo, nullptr, p_fc32, SEQ, CFC, EMB);
    gelu_split_kernel<<<SEQ * CFC / 1024, 256>>>(p_fc32, p_fc_hi, p_fc_lo);
    // 7. out = x1 + fc @ w_mlp_proj
    mma_gemm<1><<<dim3(EMB / 256, SEQ / 128), 256, gemm_smem>>>(
        p_fc_hi, p_fc_lo, p_wmlp_hi, p_wmlp_lo, p_x1, out, SEQ, EMB, CFC);
}

// round 6
// speedup vs baseline: 1.2892x; 1.2892x over previous
#include <cuda_runtime.h>
#include <cuda_bf16.h>
#include <cuda_fp16.h>
#include <mma.h>
#include <cstdint>
#include <math.h>

using namespace nvcuda;

// Block: B=1, T=4096, C=1024, H=16, hs=64
#define SEQ 4096
#define EMB 1024
#define NHEAD 16
#define HS 64
#define C3 3072
#define CFC 4096

typedef __nv_bfloat16 bf16;

// ---------------- device scratch (no allocations allowed) ----------------
__device__ bf16 g_h_hi[SEQ * EMB], g_h_lo[SEQ * EMB];        // LN out (split)
__device__ float g_qkv[SEQ * C3];                            // qkv fp32
__device__ bf16 g_attn_hi[SEQ * EMB], g_attn_lo[SEQ * EMB];  // attention out (split)
__device__ float g_x1[SEQ * EMB];                            // x + attn_proj
__device__ bf16 g_fc_hi[SEQ * CFC], g_fc_lo[SEQ * CFC];      // gelu(fc) (split)
// transposed + split weights: Wt[n][k]
__device__ bf16 g_wqkv_hi[C3 * EMB], g_wqkv_lo[C3 * EMB];
__device__ bf16 g_wproj_hi[EMB * EMB], g_wproj_lo[EMB * EMB];
__device__ bf16 g_wfc_hi[CFC * EMB], g_wfc_lo[CFC * EMB];
__device__ bf16 g_wmlp_hi[EMB * CFC], g_wmlp_lo[EMB * CFC];
// fp16 K (hi/lo) per head [hd][seq][64]; V transposed per head [hd][d][seq]
__device__ __half g_kh[NHEAD * SEQ * HS], g_kl[NHEAD * SEQ * HS];
__device__ __half g_vt[NHEAD * HS * SEQ];

__device__ __forceinline__ void split_bf16(float v, bf16& hi, bf16& lo) {
    hi = __float2bfloat16(v);
    lo = __float2bfloat16(v - __bfloat162float(hi));
}
__device__ __forceinline__ float gelu_exact(float v) {
    return 0.5f * v * (1.0f + erff(v * 0.70710678118654752440f));
}

// ---- cp.async helpers ----
__device__ __forceinline__ uint32_t smem_u32(const void* p) {
    uint32_t a;
    asm("{ .reg .u64 t; cvta.to.shared.u64 t, %1; cvt.u32.u64 %0, t; }" : "=r"(a) : "l"(p));
    return a;
}
__device__ __forceinline__ void cp16(void* sp, const void* gp) {
    asm volatile("cp.async.cg.shared.global [%0], [%1], 16;" :: "r"(smem_u32(sp)), "l"(gp));
}
__device__ __forceinline__ void cp_commit() {
    asm volatile("cp.async.commit_group;" ::: "memory");
}
__device__ __forceinline__ void cp_wait0() {
    asm volatile("cp.async.wait_group 0;" ::: "memory");
}
__device__ __forceinline__ void cp_wait1() {
    asm volatile("cp.async.wait_group 1;" ::: "memory");
}

// ---- raw mma.sync m16n8k16 fp16 -> fp32 ----
__device__ __forceinline__ void mma16816(float* c, const uint32_t* a, uint32_t b0, uint32_t b1) {
    asm volatile(
        "mma.sync.aligned.m16n8k16.row.col.f32.f16.f16.f32 "
        "{%0,%1,%2,%3}, {%4,%5,%6,%7}, {%8,%9}, {%0,%1,%2,%3};"
        : "+f"(c[0]), "+f"(c[1]), "+f"(c[2]), "+f"(c[3])
        : "r"(a[0]), "r"(a[1]), "r"(a[2]), "r"(a[3]), "r"(b0), "r"(b1));
}
__device__ __forceinline__ uint32_t pack_h2(float x, float y) {
    __half2 h = __floats2half2_rn(x, y);
    return *reinterpret_cast<uint32_t*>(&h);
}

// ---------------- LayerNorm -> split bf16 ----------------
__global__ void ln_kernel(const float* __restrict__ x, const float* __restrict__ w,
                          bf16* __restrict__ out_hi, bf16* __restrict__ out_lo) {
    const int row = blockIdx.x;
    const int tid = threadIdx.x;  // 256, 4 floats each
    const float4 v = reinterpret_cast<const float4*>(x + (size_t)row * EMB)[tid];

    float s = v.x + v.y + v.z + v.w;
    float q = v.x * v.x + v.y * v.y + v.z * v.z + v.w * v.w;
    #pragma unroll
    for (int off = 16; off > 0; off >>= 1) {
        s += __shfl_xor_sync(0xffffffffu, s, off);
        q += __shfl_xor_sync(0xffffffffu, q, off);
    }
    __shared__ float ws[8], wq[8], s_mean, s_rstd;
    const int wid = tid >> 5, lane = tid & 31;
    if (lane == 0) { ws[wid] = s; wq[wid] = q; }
    __syncthreads();
    if (tid == 0) {
        float S = 0.f, Q = 0.f;
        #pragma unroll
        for (int i = 0; i < 8; i++) { S += ws[i]; Q += wq[i]; }
        float mean = S * (1.0f / EMB);
        float var = Q * (1.0f / EMB) - mean * mean;
        s_mean = mean;
        s_rstd = rsqrtf(var + 1e-5f);
    }
    __syncthreads();
    const float mean = s_mean, rstd = s_rstd;
    const float4 g = reinterpret_cast<const float4*>(w)[tid];
    float o[4] = {(v.x - mean) * rstd * g.x, (v.y - mean) * rstd * g.y,
                  (v.z - mean) * rstd * g.z, (v.w - mean) * rstd * g.w};
    const size_t base = (size_t)row * EMB + tid * 4;
    #pragma unroll
    for (int i = 0; i < 4; i++) {
        bf16 hi, lo;
        split_bf16(o[i], hi, lo);
        out_hi[base + i] = hi;
        out_lo[base + i] = lo;
    }
}

// ---------------- weight transpose + split: W[K,N] fp32 -> Wt_hi/lo[N,K] bf16 ----------------
__global__ __launch_bounds__(256) void wt_split_kernel(const float* __restrict__ W,
                                                       bf16* __restrict__ th,
                                                       bf16* __restrict__ tl,
                                                       int K, int N) {
    __shared__ float tile[32][33];
    const int bn = blockIdx.x * 32;
    const int bk = blockIdx.y * 32;
    const int tx = threadIdx.x & 31, ty = threadIdx.x >> 5;
    #pragma unroll
    for (int r = ty; r < 32; r += 8)
        tile[r][tx] = W[(size_t)(bk + r) * N + bn + tx];
    __syncthreads();
    #pragma unroll
    for (int r = ty; r < 32; r += 8) {
        const float v = tile[tx][r];  // = W[bk+tx][bn+r]
        bf16 hi, lo;
        split_bf16(v, hi, lo);
        const size_t o = (size_t)(bn + r) * K + bk + tx;
        th[o] = hi;
        tl[o] = lo;
    }
}

// ---------------- K/V fp16 prep: split K, transpose V ----------------
__global__ __launch_bounds__(256) void kv_prep(const float* __restrict__ qkv,
                                               __half* __restrict__ kh,
                                               __half* __restrict__ kl,
                                               __half* __restrict__ vt) {
    __shared__ __half vts[64][65];
    const int sb = blockIdx.x, hd = blockIdx.y;
    const int tid = threadIdx.x;
    for (int i = tid; i < 4096; i += 256) {
        const int r = i >> 6, c = i & 63;
        const size_t base = (size_t)(sb * 64 + r) * C3 + hd * HS;
        const float k = qkv[base + EMB + c];
        const __half h = __float2half(k);
        const size_t ko = ((size_t)hd * SEQ + sb * 64 + r) * HS + c;
        kh[ko] = h;
        kl[ko] = __float2half(k - __half2float(h));
        vts[c][r] = __float2half(qkv[base + 2 * EMB + c]);
    }
    __syncthreads();
    for (int i = tid; i < 4096; i += 256) {
        const int d = i >> 6, ss = i & 63;
        vt[((size_t)hd * HS + d) * SEQ + sb * 64 + ss] = vts[d][ss];
    }
}

// ---------------- WMMA GEMM (R4 config): 128x128, KC=32, double-buffered, bf16x3 ----------------
#define KC2 32
#define SPAD 40
#define SLAB (128 * SPAD)
#define STAGE_ELEMS (4 * SLAB)

template <int EPI>
__global__ __launch_bounds__(256, 2) void mma_gemm(
    const bf16* __restrict__ Ah, const bf16* __restrict__ Al,
    const bf16* __restrict__ Bh, const bf16* __restrict__ Bl,
    const float* __restrict__ R, float* __restrict__ C,
    bf16* __restrict__ Chi, bf16* __restrict__ Clo,
    int M, int N, int K) {
    extern __shared__ char smraw[];
    bf16* sm = reinterpret_cast<bf16*>(smraw);

    const int tid = threadIdx.x;
    const int wid = tid >> 5;
    const int wm = wid & 1;
    const int wn = wid >> 1;
    const int bm = blockIdx.y * 128, bn = blockIdx.x * 128;

    wmma::fragment<wmma::accumulator, 16, 16, 16, float> acc[4][2];
    if (EPI == 1) {
        #pragma unroll
        for (int i = 0; i < 4; i++)
            #pragma unroll
            for (int j = 0; j < 2; j++)
                wmma::load_matrix_sync(
                    acc[i][j],
                    R + (size_t)(bm + wm * 64 + i * 16) * N + bn + wn * 32 + j * 16,
                    N, wmma::mem_row_major);
    } else {
        #pragma unroll
        for (int i = 0; i < 4; i++)
            #pragma unroll
            for (int j = 0; j < 2; j++)
                wmma::fill_fragment(acc[i][j], 0.0f);
    }

    const int NC = K / KC2;

    auto load_stage = [&](int buf, int k0) {
        bf16* st = sm + buf * STAGE_ELEMS;
        #pragma unroll
        for (int o = 0; o < 2; o++) {
            const int idx = tid + o * 256;
            const int row = idx >> 2, seg = idx & 3;
            const int soff = row * SPAD + seg * 8;
            const size_t ga = (size_t)(bm + row) * K + k0 + seg * 8;
            const size_t gb = (size_t)(bn + row) * K + k0 + seg * 8;
            cp16(st + soff,            Ah + ga);
            cp16(st + SLAB + soff,     Al + ga);
            cp16(st + 2 * SLAB + soff, Bh + gb);
            cp16(st + 3 * SLAB + soff, Bl + gb);
        }
    };

    load_stage(0, 0);
    cp_commit();

    for (int c = 0; c < NC; c++) {
        if (c + 1 < NC) {
            load_stage((c + 1) & 1, (c + 1) * KC2);
            cp_commit();
            cp_wait1();
        } else {
            cp_wait0();
        }
        __syncthreads();

        bf16* st = sm + (c & 1) * STAGE_ELEMS;
        bf16* sAh = st;
        bf16* sAl = st + SLAB;
        bf16* sBh = st + 2 * SLAB;
        bf16* sBl = st + 3 * SLAB;

        #pragma unroll
        for (int kk = 0; kk < KC2 / 16; kk++) {
            wmma::fragment<wmma::matrix_b, 16, 16, 16, bf16, wmma::col_major> b_hi[2], b_lo[2];
            #pragma unroll
            for (int j = 0; j < 2; j++) {
                const int nb = (wn * 32 + j * 16) * SPAD + kk * 16;
                wmma::load_matrix_sync(b_hi[j], sBh + nb, SPAD);
                wmma::load_matrix_sync(b_lo[j], sBl + nb, SPAD);
            }
            #pragma unroll
            for (int i = 0; i < 4; i++) {
                wmma::fragment<wmma::matrix_a, 16, 16, 16, bf16, wmma::row_major> a_hi, a_lo;
                const int ab = (wm * 64 + i * 16) * SPAD + kk * 16;
                wmma::load_matrix_sync(a_hi, sAh + ab, SPAD);
                wmma::load_matrix_sync(a_lo, sAl + ab, SPAD);
                #pragma unroll
                for (int j = 0; j < 2; j++) {
                    wmma::mma_sync(acc[i][j], a_hi, b_hi[j], acc[i][j]);
                    wmma::mma_sync(acc[i][j], a_hi, b_lo[j], acc[i][j]);
                    wmma::mma_sync(acc[i][j], a_lo, b_hi[j], acc[i][j]);
                }
            }
        }
        __syncthreads();
    }

    if (EPI != 2) {
        #pragma unroll
        for (int i = 0; i < 4; i++)
            #pragma unroll
            for (int j = 0; j < 2; j++)
                wmma::store_matrix_sync(
                    C + (size_t)(bm + wm * 64 + i * 16) * N + bn + wn * 32 + j * 16,
                    acc[i][j], N, wmma::mem_row_major);
    } else {
        __syncthreads();
        float* stage = reinterpret_cast<float*>(smraw);   // 128 x 132 fp32
        #pragma unroll
        for (int i = 0; i < 4; i++)
            #pragma unroll
            for (int j = 0; j < 2; j++)
                wmma::store_matrix_sync(
                    stage + (size_t)(wm * 64 + i * 16) * 132 + wn * 32 + j * 16,
                    acc[i][j], 132, wmma::mem_row_major);
        __syncthreads();
        #pragma unroll
        for (int e = 0; e < 64; e++) {
            const int idx = tid + e * 256;
            const int row = idx >> 7, col = idx & 127;
            const float gv = gelu_exact(stage[row * 132 + col]);
            bf16 hi, lo;
            split_bf16(gv, hi, lo);
            const size_t gi = (size_t)(bm + row) * N + bn + col;
            Chi[gi] = hi;
            Clo[gi] = lo;
        }
    }
}

// ---------------- FA2 flash attention: register-resident, mma.sync ----------------
// CTA: 128 threads = 4 warps, each warp owns 16 q-rows. Tile: 64q x 64k.
// S/P/O live in registers; smem only for Q staging + double-buffered Kh/Kl/Vt fp16 tiles.
#define KVPAD 72
#define KVTILE (64 * KVPAD)

__global__ __launch_bounds__(128) void flash2(
    const float* __restrict__ qkv,
    const __half* __restrict__ kh, const __half* __restrict__ kl,
    const __half* __restrict__ vt,
    bf16* __restrict__ out_hi, bf16* __restrict__ out_lo) {
    extern __shared__ char smraw[];
    __half* Qs = reinterpret_cast<__half*>(smraw);   // 64 x 72
    __half* KB = Qs + KVTILE;                        // [2 buf][Kh,Kl,Vt][64 x 72]

    const int tid = threadIdx.x;
    const int warp = tid >> 5, lane = tid & 31;
    const int gid = lane >> 2, tig = lane & 3;
    const int qb = (int)gridDim.x - 1 - (int)blockIdx.x;   // heavy tiles first
    const int hd = blockIdx.y;

    // stage Q (pre-scaled by 1/sqrt(hs)) as fp16
    for (int i = tid; i < 4096; i += 128) {
        const int r = i >> 6, c = i & 63;
        Qs[r * KVPAD + c] =
            __float2half(qkv[(size_t)(qb * 64 + r) * C3 + hd * HS + c] * 0.125f);
    }
    __syncthreads();

    // persistent Q A-fragments: qa[kk][0..3]
    uint32_t qa[4][4];
    const int row0 = warp * 16 + gid;
    #pragma unroll
    for (int kk = 0; kk < 4; kk++) {
        qa[kk][0] = *reinterpret_cast<const uint32_t*>(&Qs[row0 * KVPAD + kk * 16 + tig * 2]);
        qa[kk][1] = *reinterpret_cast<const uint32_t*>(&Qs[(row0 + 8) * KVPAD + kk * 16 + tig * 2]);
        qa[kk][2] = *reinterpret_cast<const uint32_t*>(&Qs[row0 * KVPAD + kk * 16 + 8 + tig * 2]);
        qa[kk][3] = *reinterpret_cast<const uint32_t*>(&Qs[(row0 + 8) * KVPAD + kk * 16 + 8 + tig * 2]);
    }

    float o[8][4];
    #pragma unroll
    for (int j = 0; j < 8; j++)
        #pragma unroll
        for (int t = 0; t < 4; t++) o[j][t] = 0.f;
    float m0 = -1e30f, m1 = -1e30f, l0 = 0.f, l1 = 0.f;

    const size_t khb = (size_t)hd * SEQ * HS;
    const size_t vtb = (size_t)hd * HS * SEQ;

    auto prefetch = [&](int buf, int kt) {
        __half* st = KB + buf * (3 * KVTILE);
        #pragma unroll
        for (int o2 = 0; o2 < 4; o2++) {
            const int idx = tid + o2 * 128;   // 0..511
            const int r = idx >> 3, seg = idx & 7;
            const int so = r * KVPAD + seg * 8;
            cp16(st + so,               kh + khb + (size_t)(kt * 64 + r) * HS + seg * 8);
            cp16(st + KVTILE + so,      kl + khb + (size_t)(kt * 64 + r) * HS + seg * 8);
            cp16(st + 2 * KVTILE + so,  vt + vtb + (size_t)r * SEQ + kt * 64 + seg * 8);
        }
    };

    prefetch(0, 0);
    cp_commit();

    for (int kt = 0; kt <= qb; kt++) {
        if (kt < qb) {
            prefetch((kt + 1) & 1, kt + 1);
            cp_commit();
            cp_wait1();
        } else {
            cp_wait0();
        }
        __syncthreads();

        __half* st = KB + (kt & 1) * (3 * KVTILE);
        const __half* Kh = st;
        const __half* Kl = st + KVTILE;
        const __half* Vt = st + 2 * KVTILE;

        // ---- S = Q @ K^T (K hi/lo 2-pass) ----
        float s[8][4];
        #pragma unroll
        for (int j = 0; j < 8; j++)
            #pragma unroll
            for (int t = 0; t < 4; t++) s[j][t] = 0.f;
        #pragma unroll
        for (int kk = 0; kk < 4; kk++)
            #pragma unroll
            for (int j = 0; j < 8; j++) {
                const int off = (j * 8 + gid) * KVPAD + kk * 16 + tig * 2;
                uint32_t b0 = *reinterpret_cast<const uint32_t*>(&Kh[off]);
                uint32_t b1 = *reinterpret_cast<const uint32_t*>(&Kh[off + 8]);
                mma16816(s[j], qa[kk], b0, b1);
                b0 = *reinterpret_cast<const uint32_t*>(&Kl[off]);
                b1 = *reinterpret_cast<const uint32_t*>(&Kl[off + 8]);
                mma16816(s[j], qa[kk], b0, b1);
            }

        // ---- causal mask (diag tile only) ----
        if (kt == qb) {
            #pragma unroll
            for (int j = 0; j < 8; j++) {
                const int c0 = j * 8 + tig * 2;
                if (c0 > row0)         s[j][0] = -1e30f;
                if (c0 + 1 > row0)     s[j][1] = -1e30f;
                if (c0 > row0 + 8)     s[j][2] = -1e30f;
                if (c0 + 1 > row0 + 8) s[j][3] = -1e30f;
            }
        }

        // ---- online softmax (registers + quad shuffles) ----
        float mx0 = -1e30f, mx1 = -1e30f;
        #pragma unroll
        for (int j = 0; j < 8; j++) {
            mx0 = fmaxf(mx0, fmaxf(s[j][0], s[j][1]));
            mx1 = fmaxf(mx1, fmaxf(s[j][2], s[j][3]));
        }
        mx0 = fmaxf(mx0, __shfl_xor_sync(0xffffffffu, mx0, 1));
        mx0 = fmaxf(mx0, __shfl_xor_sync(0xffffffffu, mx0, 2));
        mx1 = fmaxf(mx1, __shfl_xor_sync(0xffffffffu, mx1, 1));
        mx1 = fmaxf(mx1, __shfl_xor_sync(0xffffffffu, mx1, 2));
        const float mn0 = fmaxf(m0, mx0), mn1 = fmaxf(m1, mx1);
        const float al0 = __expf(m0 - mn0), al1 = __expf(m1 - mn1);
        float rs0 = 0.f, rs1 = 0.f;
        #pragma unroll
        for (int j = 0; j < 8; j++) {
            s[j][0] = __expf(s[j][0] - mn0);
            s[j][1] = __expf(s[j][1] - mn0);
            s[j][2] = __expf(s[j][2] - mn1);
            s[j][3] = __expf(s[j][3] - mn1);
            rs0 += s[j][0] + s[j][1];
            rs1 += s[j][2] + s[j][3];
        }
        rs0 += __shfl_xor_sync(0xffffffffu, rs0, 1);
        rs0 += __shfl_xor_sync(0xffffffffu, rs0, 2);
        rs1 += __shfl_xor_sync(0xffffffffu, rs1, 1);
        rs1 += __shfl_xor_sync(0xffffffffu, rs1, 2);
        l0 = l0 * al0 + rs0;
        l1 = l1 * al1 + rs1;
        m0 = mn0;
        m1 = mn1;
        #pragma unroll
        for (int j = 0; j < 8; j++) {
            o[j][0] *= al0; o[j][1] *= al0;
            o[j][2] *= al1; o[j][3] *= al1;
        }

        // ---- O += P @ V (P repacked acc->A in registers) ----
        #pragma unroll
        for (int kk = 0; kk < 4; kk++) {
            uint32_t pa[4];
            pa[0] = pack_h2(s[2 * kk][0], s[2 * kk][1]);
            pa[1] = pack_h2(s[2 * kk][2], s[2 * kk][3]);
            pa[2] = pack_h2(s[2 * kk + 1][0], s[2 * kk + 1][1]);
            pa[3] = pack_h2(s[2 * kk + 1][2], s[2 * kk + 1][3]);
            #pragma unroll
            for (int j = 0; j < 8; j++) {
                const int off = (j * 8 + gid) * KVPAD + kk * 16 + tig * 2;
                const uint32_t b0 = *reinterpret_cast<const uint32_t*>(&Vt[off]);
                const uint32_t b1 = *reinterpret_cast<const uint32_t*>(&Vt[off + 8]);
                mma16816(o[j], pa, b0, b1);
            }
        }
        __syncthreads();   // all reads of this stage done before it is overwritten
    }

    // ---- finalize: O / l, split bf16, direct stores (half2-pair granularity) ----
    const float inv0 = 1.0f / l0, inv1 = 1.0f / l1;
    #pragma unroll
    for (int j = 0; j < 8; j++) {
        const int d = hd * HS + j * 8 + tig * 2;
        const size_t r0o = (size_t)(qb * 64 + row0) * EMB + d;
        const size_t r1o = (size_t)(qb * 64 + row0 + 8) * EMB + d;
        bf16 h0, lo0, h1, lo1;
        split_bf16(o[j][0] * inv0, h0, lo0);
        split_bf16(o[j][1] * inv0, h1, lo1);
        *reinterpret_cast<__nv_bfloat162*>(&out_hi[r0o]) = __nv_bfloat162(h0, h1);
        *reinterpret_cast<__nv_bfloat162*>(&out_lo[r0o]) = __nv_bfloat162(lo0, lo1);
        split_bf16(o[j][2] * inv1, h0, lo0);
        split_bf16(o[j][3] * inv1, h1, lo1);
        *reinterpret_cast<__nv_bfloat162*>(&out_hi[r1o]) = __nv_bfloat162(h0, h1);
        *reinterpret_cast<__nv_bfloat162*>(&out_lo[r1o]) = __nv_bfloat162(lo0, lo1);
    }
}

// ---------------- launch ----------------
extern "C" void kernel_launch(void* const* d_in, const int* in_sizes, int n_in,
                              void* d_out, int out_size) {
    const float* x           = (const float*)d_in[0];
    const float* w_qkv       = (const float*)d_in[1];
    const float* w_attn_proj = (const float*)d_in[2];
    const float* w_fc        = (const float*)d_in[3];
    const float* w_mlp_proj  = (const float*)d_in[4];
    const float* ln1_w       = (const float*)d_in[5];
    const float* ln2_w       = (const float*)d_in[6];
    float* out = (float*)d_out;

    bf16 *p_h_hi, *p_h_lo, *p_attn_hi, *p_attn_lo, *p_fc_hi, *p_fc_lo;
    bf16 *p_wqkv_hi, *p_wqkv_lo, *p_wproj_hi, *p_wproj_lo;
    bf16 *p_wfc_hi, *p_wfc_lo, *p_wmlp_hi, *p_wmlp_lo;
    float *p_qkv, *p_x1;
    __half *p_kh, *p_kl, *p_vt;
    cudaGetSymbolAddress((void**)&p_h_hi, g_h_hi);
    cudaGetSymbolAddress((void**)&p_h_lo, g_h_lo);
    cudaGetSymbolAddress((void**)&p_qkv, g_qkv);
    cudaGetSymbolAddress((void**)&p_attn_hi, g_attn_hi);
    cudaGetSymbolAddress((void**)&p_attn_lo, g_attn_lo);
    cudaGetSymbolAddress((void**)&p_x1, g_x1);
    cudaGetSymbolAddress((void**)&p_fc_hi, g_fc_hi);
    cudaGetSymbolAddress((void**)&p_fc_lo, g_fc_lo);
    cudaGetSymbolAddress((void**)&p_wqkv_hi, g_wqkv_hi);
    cudaGetSymbolAddress((void**)&p_wqkv_lo, g_wqkv_lo);
    cudaGetSymbolAddress((void**)&p_wproj_hi, g_wproj_hi);
    cudaGetSymbolAddress((void**)&p_wproj_lo, g_wproj_lo);
    cudaGetSymbolAddress((void**)&p_wfc_hi, g_wfc_hi);
    cudaGetSymbolAddress((void**)&p_wfc_lo, g_wfc_lo);
    cudaGetSymbolAddress((void**)&p_wmlp_hi, g_wmlp_hi);
    cudaGetSymbolAddress((void**)&p_wmlp_lo, g_wmlp_lo);
    cudaGetSymbolAddress((void**)&p_kh, g_kh);
    cudaGetSymbolAddress((void**)&p_kl, g_kl);
    cudaGetSymbolAddress((void**)&p_vt, g_vt);

    const int gemm_smem = 2 * STAGE_ELEMS * (int)sizeof(bf16);          // 81,920 B
    cudaFuncSetAttribute(mma_gemm<0>, cudaFuncAttributeMaxDynamicSharedMemorySize, gemm_smem);
    cudaFuncSetAttribute(mma_gemm<1>, cudaFuncAttributeMaxDynamicSharedMemorySize, gemm_smem);
    cudaFuncSetAttribute(mma_gemm<2>, cudaFuncAttributeMaxDynamicSharedMemorySize, gemm_smem);
    const int flash_smem = (KVTILE + 2 * 3 * KVTILE) * (int)sizeof(__half);  // 64,512 B
    cudaFuncSetAttribute(flash2, cudaFuncAttributeMaxDynamicSharedMemorySize, flash_smem);

    // 0. weight transpose + split
    wt_split_kernel<<<dim3(C3 / 32, EMB / 32), 256>>>(w_qkv, p_wqkv_hi, p_wqkv_lo, EMB, C3);
    wt_split_kernel<<<dim3(EMB / 32, EMB / 32), 256>>>(w_attn_proj, p_wproj_hi, p_wproj_lo, EMB, EMB);
    wt_split_kernel<<<dim3(CFC / 32, EMB / 32), 256>>>(w_fc, p_wfc_hi, p_wfc_lo, EMB, CFC);
    wt_split_kernel<<<dim3(EMB / 32, CFC / 32), 256>>>(w_mlp_proj, p_wmlp_hi, p_wmlp_lo, CFC, EMB);

    // 1. h = LN(x, ln1)
    ln_kernel<<<SEQ, 256>>>(x, ln1_w, p_h_hi, p_h_lo);
    // 2. qkv = h @ w_qkv
    mma_gemm<0><<<dim3(C3 / 128, SEQ / 128), 256, gemm_smem>>>(
        p_h_hi, p_h_lo, p_wqkv_hi, p_wqkv_lo, nullptr, p_qkv, nullptr, nullptr, SEQ, C3, EMB);
    // 3a. K/V fp16 prep
    kv_prep<<<dim3(SEQ / 64, NHEAD), 256>>>(p_qkv, p_kh, p_kl, p_vt);
    // 3b. attention (FA2, register-resident)
    flash2<<<dim3(SEQ / 64, NHEAD), 128, flash_smem>>>(p_qkv, p_kh, p_kl, p_vt, p_attn_hi, p_attn_lo);
    // 4. x1 = x + attn @ w_attn_proj
    mma_gemm<1><<<dim3(EMB / 128, SEQ / 128), 256, gemm_smem>>>(
        p_attn_hi, p_attn_lo, p_wproj_hi, p_wproj_lo, x, p_x1, nullptr, nullptr, SEQ, EMB, EMB);
    // 5. h = LN(x1, ln2)
    ln_kernel<<<SEQ, 256>>>(p_x1, ln2_w, p_h_hi, p_h_lo);
    // 6. fc = gelu(h @ w_fc)  (fused epilogue)
    mma_gemm<2><<<dim3(CFC / 128, SEQ / 128), 256, gemm_smem>>>(
        p_h_hi, p_h_lo, p_wfc_hi, p_wfc_lo, nullptr, nullptr, p_fc_hi, p_fc_lo, SEQ, CFC, EMB);
    // 7. out = x1 + fc @ w_mlp_proj
    mma_gemm<1><<<dim3(EMB / 128, SEQ / 128), 256, gemm_smem>>>(
        p_fc_hi, p_fc_lo, p_wmlp_hi, p_wmlp_lo, p_x1, out, nullptr, nullptr, SEQ, EMB, CFC);
}

// round 7
// speedup vs baseline: 1.4313x; 1.1102x over previous
#include <cuda_runtime.h>
#include <cuda_bf16.h>
#include <cuda_fp16.h>
#include <cstdint>
#include <math.h>

// Block: B=1, T=4096, C=1024, H=16, hs=64
#define SEQ 4096
#define EMB 1024
#define NHEAD 16
#define HS 64
#define C3 3072
#define CFC 4096

typedef __nv_bfloat16 bf16;

// ---------------- device scratch (no allocations allowed) ----------------
__device__ bf16 g_h_hi[SEQ * EMB], g_h_lo[SEQ * EMB];        // LN out (split)
__device__ float g_qkv[SEQ * C3];                            // qkv fp32
__device__ bf16 g_attn_hi[SEQ * EMB], g_attn_lo[SEQ * EMB];  // attention out (split)
__device__ float g_x1[SEQ * EMB];                            // x + attn_proj
__device__ bf16 g_fc_hi[SEQ * CFC], g_fc_lo[SEQ * CFC];      // gelu(fc) (split)
// transposed + split weights: Wt[n][k]
__device__ bf16 g_wqkv_hi[C3 * EMB], g_wqkv_lo[C3 * EMB];
__device__ bf16 g_wproj_hi[EMB * EMB], g_wproj_lo[EMB * EMB];
__device__ bf16 g_wfc_hi[CFC * EMB], g_wfc_lo[CFC * EMB];
__device__ bf16 g_wmlp_hi[EMB * CFC], g_wmlp_lo[EMB * CFC];
// fp16 K (hi/lo) per head [hd][seq][64]; V transposed per head [hd][d][seq]
__device__ __half g_kh[NHEAD * SEQ * HS], g_kl[NHEAD * SEQ * HS];
__device__ __half g_vt[NHEAD * HS * SEQ];

__device__ __forceinline__ void split_bf16(float v, bf16& hi, bf16& lo) {
    hi = __float2bfloat16(v);
    lo = __float2bfloat16(v - __bfloat162float(hi));
}
__device__ __forceinline__ float gelu_exact(float v) {
    return 0.5f * v * (1.0f + erff(v * 0.70710678118654752440f));
}

// ---- smem/cp.async/mma helpers ----
__device__ __forceinline__ uint32_t smem_u32(const void* p) {
    uint32_t a;
    asm("{ .reg .u64 t; cvta.to.shared.u64 t, %1; cvt.u32.u64 %0, t; }" : "=r"(a) : "l"(p));
    return a;
}
__device__ __forceinline__ void cp16(void* sp, const void* gp) {
    asm volatile("cp.async.cg.shared.global [%0], [%1], 16;" :: "r"(smem_u32(sp)), "l"(gp));
}
__device__ __forceinline__ void cp_commit() {
    asm volatile("cp.async.commit_group;" ::: "memory");
}
__device__ __forceinline__ void cp_wait0() {
    asm volatile("cp.async.wait_group 0;" ::: "memory");
}
__device__ __forceinline__ void cp_wait1() {
    asm volatile("cp.async.wait_group 1;" ::: "memory");
}
__device__ __forceinline__ void ldsm4(uint32_t* r, uint32_t addr) {
    asm volatile("ldmatrix.sync.aligned.m8n8.x4.shared.b16 {%0,%1,%2,%3}, [%4];"
                 : "=r"(r[0]), "=r"(r[1]), "=r"(r[2]), "=r"(r[3]) : "r"(addr));
}
// fp16 HMMA (flash)
__device__ __forceinline__ void mma16816(float* c, const uint32_t* a, uint32_t b0, uint32_t b1) {
    asm volatile(
        "mma.sync.aligned.m16n8k16.row.col.f32.f16.f16.f32 "
        "{%0,%1,%2,%3}, {%4,%5,%6,%7}, {%8,%9}, {%0,%1,%2,%3};"
        : "+f"(c[0]), "+f"(c[1]), "+f"(c[2]), "+f"(c[3])
        : "r"(a[0]), "r"(a[1]), "r"(a[2]), "r"(a[3]), "r"(b0), "r"(b1));
}
// bf16 HMMA (gemm)
__device__ __forceinline__ void mma16816b(float* c, const uint32_t* a, uint32_t b0, uint32_t b1) {
    asm volatile(
        "mma.sync.aligned.m16n8k16.row.col.f32.bf16.bf16.f32 "
        "{%0,%1,%2,%3}, {%4,%5,%6,%7}, {%8,%9}, {%0,%1,%2,%3};"
        : "+f"(c[0]), "+f"(c[1]), "+f"(c[2]), "+f"(c[3])
        : "r"(a[0]), "r"(a[1]), "r"(a[2]), "r"(a[3]), "r"(b0), "r"(b1));
}
__device__ __forceinline__ uint32_t pack_h2(float x, float y) {
    __half2 h = __floats2half2_rn(x, y);
    return *reinterpret_cast<uint32_t*>(&h);
}

// ---------------- LayerNorm -> split bf16 ----------------
__global__ void ln_kernel(const float* __restrict__ x, const float* __restrict__ w,
                          bf16* __restrict__ out_hi, bf16* __restrict__ out_lo) {
    const int row = blockIdx.x;
    const int tid = threadIdx.x;  // 256, 4 floats each
    const float4 v = reinterpret_cast<const float4*>(x + (size_t)row * EMB)[tid];

    float s = v.x + v.y + v.z + v.w;
    float q = v.x * v.x + v.y * v.y + v.z * v.z + v.w * v.w;
    #pragma unroll
    for (int off = 16; off > 0; off >>= 1) {
        s += __shfl_xor_sync(0xffffffffu, s, off);
        q += __shfl_xor_sync(0xffffffffu, q, off);
    }
    __shared__ float ws[8], wq[8], s_mean, s_rstd;
    const int wid = tid >> 5, lane = tid & 31;
    if (lane == 0) { ws[wid] = s; wq[wid] = q; }
    __syncthreads();
    if (tid == 0) {
        float S = 0.f, Q = 0.f;
        #pragma unroll
        for (int i = 0; i < 8; i++) { S += ws[i]; Q += wq[i]; }
        float mean = S * (1.0f / EMB);
        float var = Q * (1.0f / EMB) - mean * mean;
        s_mean = mean;
        s_rstd = rsqrtf(var + 1e-5f);
    }
    __syncthreads();
    const float mean = s_mean, rstd = s_rstd;
    const float4 g = reinterpret_cast<const float4*>(w)[tid];
    float o[4] = {(v.x - mean) * rstd * g.x, (v.y - mean) * rstd * g.y,
                  (v.z - mean) * rstd * g.z, (v.w - mean) * rstd * g.w};
    const size_t base = (size_t)row * EMB + tid * 4;
    #pragma unroll
    for (int i = 0; i < 4; i++) {
        bf16 hi, lo;
        split_bf16(o[i], hi, lo);
        out_hi[base + i] = hi;
        out_lo[base + i] = lo;
    }
}

// ---------------- weight transpose + split: W[K,N] fp32 -> Wt_hi/lo[N,K] bf16 ----------------
__global__ __launch_bounds__(256) void wt_split_kernel(const float* __restrict__ W,
                                                       bf16* __restrict__ th,
                                                       bf16* __restrict__ tl,
                                                       int K, int N) {
    __shared__ float tile[32][33];
    const int bn = blockIdx.x * 32;
    const int bk = blockIdx.y * 32;
    const int tx = threadIdx.x & 31, ty = threadIdx.x >> 5;
    #pragma unroll
    for (int r = ty; r < 32; r += 8)
        tile[r][tx] = W[(size_t)(bk + r) * N + bn + tx];
    __syncthreads();
    #pragma unroll
    for (int r = ty; r < 32; r += 8) {
        const float v = tile[tx][r];  // = W[bk+tx][bn+r]
        bf16 hi, lo;
        split_bf16(v, hi, lo);
        const size_t o = (size_t)(bn + r) * K + bk + tx;
        th[o] = hi;
        tl[o] = lo;
    }
}

// ---------------- K/V fp16 prep: split K, transpose V ----------------
__global__ __launch_bounds__(256) void kv_prep(const float* __restrict__ qkv,
                                               __half* __restrict__ kh,
                                               __half* __restrict__ kl,
                                               __half* __restrict__ vt) {
    __shared__ __half vts[64][65];
    const int sb = blockIdx.x, hd = blockIdx.y;
    const int tid = threadIdx.x;
    for (int i = tid; i < 4096; i += 256) {
        const int r = i >> 6, c = i & 63;
        const size_t base = (size_t)(sb * 64 + r) * C3 + hd * HS;
        const float k = qkv[base + EMB + c];
        const __half h = __float2half(k);
        const size_t ko = ((size_t)hd * SEQ + sb * 64 + r) * HS + c;
        kh[ko] = h;
        kl[ko] = __float2half(k - __half2float(h));
        vts[c][r] = __float2half(qkv[base + 2 * EMB + c]);
    }
    __syncthreads();
    for (int i = tid; i < 4096; i += 256) {
        const int d = i >> 6, ss = i & 63;
        vt[((size_t)hd * HS + d) * SEQ + sb * 64 + ss] = vts[d][ss];
    }
}

// ---------------- raw-MMA GEMM: 128x128 CTA (4 warps, 64x64 warp tile), KC=32, bf16x3 ----------------
// C[M,N] = A[M,K] @ Wt[N,K]^T.  EPI: 0 = fp32 C, 1 = C = R + acc, 2 = gelu(acc)->split bf16
#define KC2 32
#define SPAD 40                         // conflict-free for ldmatrix (80B row stride)
#define SLAB (128 * SPAD)
#define STAGE_ELEMS (4 * SLAB)

template <int EPI>
__global__ __launch_bounds__(128, 2) void mma_gemm(
    const bf16* __restrict__ Ah, const bf16* __restrict__ Al,
    const bf16* __restrict__ Bh, const bf16* __restrict__ Bl,
    const float* __restrict__ R, float* __restrict__ C,
    bf16* __restrict__ Chi, bf16* __restrict__ Clo,
    int M, int N, int K) {
    extern __shared__ char smraw[];
    bf16* sm = reinterpret_cast<bf16*>(smraw);
    const uint32_t smb = smem_u32(sm);

    const int tid = threadIdx.x;
    const int warp = tid >> 5, lane = tid & 31;
    const int wm = warp & 1;        // 2 warps in M (64 rows)
    const int wn = warp >> 1;       // 2 warps in N (64 cols)
    const int gid = lane >> 2, tig = lane & 3;
    const int bm = blockIdx.y * 128, bn = blockIdx.x * 128;

    float acc[4][8][4];             // [mt 16rows][nt 8cols][frag]
    if (EPI == 1) {
        #pragma unroll
        for (int mt = 0; mt < 4; mt++) {
            const size_t r0 = (size_t)(bm + wm * 64 + mt * 16 + gid) * N;
            const size_t r1 = r0 + 8 * N;
            #pragma unroll
            for (int nt = 0; nt < 8; nt++) {
                const int col = bn + wn * 64 + nt * 8 + tig * 2;
                const float2 v0 = *reinterpret_cast<const float2*>(R + r0 + col);
                const float2 v1 = *reinterpret_cast<const float2*>(R + r1 + col);
                acc[mt][nt][0] = v0.x; acc[mt][nt][1] = v0.y;
                acc[mt][nt][2] = v1.x; acc[mt][nt][3] = v1.y;
            }
        }
    } else {
        #pragma unroll
        for (int mt = 0; mt < 4; mt++)
            #pragma unroll
            for (int nt = 0; nt < 8; nt++)
                #pragma unroll
                for (int t = 0; t < 4; t++) acc[mt][nt][t] = 0.f;
    }

    const int NC = K / KC2;

    // stage loader: 4 slabs x 128 rows x 32 cols (64B/row = 4 cp16) -> 16 cp16/thread
    auto load_stage = [&](int buf, int k0) {
        bf16* st = sm + buf * STAGE_ELEMS;
        #pragma unroll
        for (int o = 0; o < 4; o++) {
            const int idx = tid + o * 128;       // 0..511
            const int row = idx >> 2, seg = idx & 3;
            const int soff = row * SPAD + seg * 8;
            const size_t ga = (size_t)(bm + row) * K + k0 + seg * 8;
            const size_t gb = (size_t)(bn + row) * K + k0 + seg * 8;
            cp16(st + soff,            Ah + ga);
            cp16(st + SLAB + soff,     Al + ga);
            cp16(st + 2 * SLAB + soff, Bh + gb);
            cp16(st + 3 * SLAB + soff, Bl + gb);
        }
    };

    // ldmatrix lane address components (in elements)
    const int a_row = wm * 64 + (lane & 15);            // + mt*16
    const int a_col = (lane >> 4) << 3;                 // + kk*16
    const int b_row = wn * 64 + (lane & 7) + ((lane >> 4) << 3);  // + p*16
    const int b_col = ((lane >> 3) & 1) << 3;           // + kk*16

    load_stage(0, 0);
    cp_commit();

    for (int c = 0; c < NC; c++) {
        if (c + 1 < NC) {
            load_stage((c + 1) & 1, (c + 1) * KC2);
            cp_commit();
            cp_wait1();
        } else {
            cp_wait0();
        }
        __syncthreads();

        const uint32_t st = smb + (c & 1) * STAGE_ELEMS * 2;  // bytes
        const uint32_t sAh = st;
        const uint32_t sAl = st + SLAB * 2;
        const uint32_t sBh = st + 2 * SLAB * 2;
        const uint32_t sBl = st + 3 * SLAB * 2;

        #pragma unroll
        for (int kk = 0; kk < KC2 / 16; kk++) {
            // B fragments: 4 ldsm4 per buffer cover all 8 nt tiles
            uint32_t bh[8][2], bl[8][2];
            #pragma unroll
            for (int p = 0; p < 4; p++) {
                const uint32_t boff =
                    ((b_row + p * 16) * SPAD + kk * 16 + b_col) * 2;
                uint32_t t4[4];
                ldsm4(t4, sBh + boff);
                bh[2 * p][0] = t4[0]; bh[2 * p][1] = t4[1];
                bh[2 * p + 1][0] = t4[2]; bh[2 * p + 1][1] = t4[3];
                ldsm4(t4, sBl + boff);
                bl[2 * p][0] = t4[0]; bl[2 * p][1] = t4[1];
                bl[2 * p + 1][0] = t4[2]; bl[2 * p + 1][1] = t4[3];
            }
            #pragma unroll
            for (int mt = 0; mt < 4; mt++) {
                const uint32_t aoff =
                    ((a_row + mt * 16) * SPAD + kk * 16 + a_col) * 2;
                uint32_t ah[4], al[4];
                ldsm4(ah, sAh + aoff);
                ldsm4(al, sAl + aoff);
                #pragma unroll
                for (int nt = 0; nt < 8; nt++) {
                    mma16816b(acc[mt][nt], ah, bh[nt][0], bh[nt][1]);
                    mma16816b(acc[mt][nt], ah, bl[nt][0], bl[nt][1]);
                    mma16816b(acc[mt][nt], al, bh[nt][0], bh[nt][1]);
                }
            }
        }
        __syncthreads();
    }

    // ---- register epilogue ----
    #pragma unroll
    for (int mt = 0; mt < 4; mt++) {
        const size_t r0 = (size_t)(bm + wm * 64 + mt * 16 + gid) * N;
        const size_t r1 = r0 + 8 * N;
        #pragma unroll
        for (int nt = 0; nt < 8; nt++) {
            const int col = bn + wn * 64 + nt * 8 + tig * 2;
            if (EPI != 2) {
                *reinterpret_cast<float2*>(C + r0 + col) =
                    make_float2(acc[mt][nt][0], acc[mt][nt][1]);
                *reinterpret_cast<float2*>(C + r1 + col) =
                    make_float2(acc[mt][nt][2], acc[mt][nt][3]);
            } else {
                bf16 h0, l0, h1, l1;
                split_bf16(gelu_exact(acc[mt][nt][0]), h0, l0);
                split_bf16(gelu_exact(acc[mt][nt][1]), h1, l1);
                *reinterpret_cast<__nv_bfloat162*>(&Chi[r0 + col]) = __nv_bfloat162(h0, h1);
                *reinterpret_cast<__nv_bfloat162*>(&Clo[r0 + col]) = __nv_bfloat162(l0, l1);
                split_bf16(gelu_exact(acc[mt][nt][2]), h0, l0);
                split_bf16(gelu_exact(acc[mt][nt][3]), h1, l1);
                *reinterpret_cast<__nv_bfloat162*>(&Chi[r1 + col]) = __nv_bfloat162(h0, h1);
                *reinterpret_cast<__nv_bfloat162*>(&Clo[r1 + col]) = __nv_bfloat162(l0, l1);
            }
        }
    }
}

// ---------------- FA2 flash attention: register-resident, mma.sync (unchanged R6) ----------------
#define KVPAD 72
#define KVTILE (64 * KVPAD)

__global__ __launch_bounds__(128) void flash2(
    const float* __restrict__ qkv,
    const __half* __restrict__ kh, const __half* __restrict__ kl,
    const __half* __restrict__ vt,
    bf16* __restrict__ out_hi, bf16* __restrict__ out_lo) {
    extern __shared__ char smraw[];
    __half* Qs = reinterpret_cast<__half*>(smraw);   // 64 x 72
    __half* KB = Qs + KVTILE;                        // [2 buf][Kh,Kl,Vt][64 x 72]

    const int tid = threadIdx.x;
    const int warp = tid >> 5, lane = tid & 31;
    const int gid = lane >> 2, tig = lane & 3;
    const int qb = (int)gridDim.x - 1 - (int)blockIdx.x;   // heavy tiles first
    const int hd = blockIdx.y;

    for (int i = tid; i < 4096; i += 128) {
        const int r = i >> 6, c = i & 63;
        Qs[r * KVPAD + c] =
            __float2half(qkv[(size_t)(qb * 64 + r) * C3 + hd * HS + c] * 0.125f);
    }
    __syncthreads();

    uint32_t qa[4][4];
    const int row0 = warp * 16 + gid;
    #pragma unroll
    for (int kk = 0; kk < 4; kk++) {
        qa[kk][0] = *reinterpret_cast<const uint32_t*>(&Qs[row0 * KVPAD + kk * 16 + tig * 2]);
        qa[kk][1] = *reinterpret_cast<const uint32_t*>(&Qs[(row0 + 8) * KVPAD + kk * 16 + tig * 2]);
        qa[kk][2] = *reinterpret_cast<const uint32_t*>(&Qs[row0 * KVPAD + kk * 16 + 8 + tig * 2]);
        qa[kk][3] = *reinterpret_cast<const uint32_t*>(&Qs[(row0 + 8) * KVPAD + kk * 16 + 8 + tig * 2]);
    }

    float o[8][4];
    #pragma unroll
    for (int j = 0; j < 8; j++)
        #pragma unroll
        for (int t = 0; t < 4; t++) o[j][t] = 0.f;
    float m0 = -1e30f, m1 = -1e30f, l0 = 0.f, l1 = 0.f;

    const size_t khb = (size_t)hd * SEQ * HS;
    const size_t vtb = (size_t)hd * HS * SEQ;

    auto prefetch = [&](int buf, int kt) {
        __half* st = KB + buf * (3 * KVTILE);
        #pragma unroll
        for (int o2 = 0; o2 < 4; o2++) {
            const int idx = tid + o2 * 128;
            const int r = idx >> 3, seg = idx & 7;
            const int so = r * KVPAD + seg * 8;
            cp16(st + so,               kh + khb + (size_t)(kt * 64 + r) * HS + seg * 8);
            cp16(st + KVTILE + so,      kl + khb + (size_t)(kt * 64 + r) * HS + seg * 8);
            cp16(st + 2 * KVTILE + so,  vt + vtb + (size_t)r * SEQ + kt * 64 + seg * 8);
        }
    };

    prefetch(0, 0);
    cp_commit();

    for (int kt = 0; kt <= qb; kt++) {
        if (kt < qb) {
            prefetch((kt + 1) & 1, kt + 1);
            cp_commit();
            cp_wait1();
        } else {
            cp_wait0();
        }
        __syncthreads();

        __half* st = KB + (kt & 1) * (3 * KVTILE);
        const __half* Kh = st;
        const __half* Kl = st + KVTILE;
        const __half* Vt = st + 2 * KVTILE;

        float s[8][4];
        #pragma unroll
        for (int j = 0; j < 8; j++)
            #pragma unroll
            for (int t = 0; t < 4; t++) s[j][t] = 0.f;
        #pragma unroll
        for (int kk = 0; kk < 4; kk++)
            #pragma unroll
            for (int j = 0; j < 8; j++) {
                const int off = (j * 8 + gid) * KVPAD + kk * 16 + tig * 2;
                uint32_t b0 = *reinterpret_cast<const uint32_t*>(&Kh[off]);
                uint32_t b1 = *reinterpret_cast<const uint32_t*>(&Kh[off + 8]);
                mma16816(s[j], qa[kk], b0, b1);
                b0 = *reinterpret_cast<const uint32_t*>(&Kl[off]);
                b1 = *reinterpret_cast<const uint32_t*>(&Kl[off + 8]);
                mma16816(s[j], qa[kk], b0, b1);
            }

        if (kt == qb) {
            #pragma unroll
            for (int j = 0; j < 8; j++) {
                const int c0 = j * 8 + tig * 2;
                if (c0 > row0)         s[j][0] = -1e30f;
                if (c0 + 1 > row0)     s[j][1] = -1e30f;
                if (c0 > row0 + 8)     s[j][2] = -1e30f;
                if (c0 + 1 > row0 + 8) s[j][3] = -1e30f;
            }
        }

        float mx0 = -1e30f, mx1 = -1e30f;
        #pragma unroll
        for (int j = 0; j < 8; j++) {
            mx0 = fmaxf(mx0, fmaxf(s[j][0], s[j][1]));
            mx1 = fmaxf(mx1, fmaxf(s[j][2], s[j][3]));
        }
        mx0 = fmaxf(mx0, __shfl_xor_sync(0xffffffffu, mx0, 1));
        mx0 = fmaxf(mx0, __shfl_xor_sync(0xffffffffu, mx0, 2));
        mx1 = fmaxf(mx1, __shfl_xor_sync(0xffffffffu, mx1, 1));
        mx1 = fmaxf(mx1, __shfl_xor_sync(0xffffffffu, mx1, 2));
        const float mn0 = fmaxf(m0, mx0), mn1 = fmaxf(m1, mx1);
        const float al0 = __expf(m0 - mn0), al1 = __expf(m1 - mn1);
        float rs0 = 0.f, rs1 = 0.f;
        #pragma unroll
        for (int j = 0; j < 8; j++) {
            s[j][0] = __expf(s[j][0] - mn0);
            s[j][1] = __expf(s[j][1] - mn0);
            s[j][2] = __expf(s[j][2] - mn1);
            s[j][3] = __expf(s[j][3] - mn1);
            rs0 += s[j][0] + s[j][1];
            rs1 += s[j][2] + s[j][3];
        }
        rs0 += __shfl_xor_sync(0xffffffffu, rs0, 1);
        rs0 += __shfl_xor_sync(0xffffffffu, rs0, 2);
        rs1 += __shfl_xor_sync(0xffffffffu, rs1, 1);
        rs1 += __shfl_xor_sync(0xffffffffu, rs1, 2);
        l0 = l0 * al0 + rs0;
        l1 = l1 * al1 + rs1;
        m0 = mn0;
        m1 = mn1;
        #pragma unroll
        for (int j = 0; j < 8; j++) {
            o[j][0] *= al0; o[j][1] *= al0;
            o[j][2] *= al1; o[j][3] *= al1;
        }

        #pragma unroll
        for (int kk = 0; kk < 4; kk++) {
            uint32_t pa[4];
            pa[0] = pack_h2(s[2 * kk][0], s[2 * kk][1]);
            pa[1] = pack_h2(s[2 * kk][2], s[2 * kk][3]);
            pa[2] = pack_h2(s[2 * kk + 1][0], s[2 * kk + 1][1]);
            pa[3] = pack_h2(s[2 * kk + 1][2], s[2 * kk + 1][3]);
            #pragma unroll
            for (int j = 0; j < 8; j++) {
                const int off = (j * 8 + gid) * KVPAD + kk * 16 + tig * 2;
                const uint32_t b0 = *reinterpret_cast<const uint32_t*>(&Vt[off]);
                const uint32_t b1 = *reinterpret_cast<const uint32_t*>(&Vt[off + 8]);
                mma16816(o[j], pa, b0, b1);
            }
        }
        __syncthreads();
    }

    const float inv0 = 1.0f / l0, inv1 = 1.0f / l1;
    #pragma unroll
    for (int j = 0; j < 8; j++) {
        const int d = hd * HS + j * 8 + tig * 2;
        const size_t r0o = (size_t)(qb * 64 + row0) * EMB + d;
        const size_t r1o = (size_t)(qb * 64 + row0 + 8) * EMB + d;
        bf16 h0, lo0, h1, lo1;
        split_bf16(o[j][0] * inv0, h0, lo0);
        split_bf16(o[j][1] * inv0, h1, lo1);
        *reinterpret_cast<__nv_bfloat162*>(&out_hi[r0o]) = __nv_bfloat162(h0, h1);
        *reinterpret_cast<__nv_bfloat162*>(&out_lo[r0o]) = __nv_bfloat162(lo0, lo1);
        split_bf16(o[j][2] * inv1, h0, lo0);
        split_bf16(o[j][3] * inv1, h1, lo1);
        *reinterpret_cast<__nv_bfloat162*>(&out_hi[r1o]) = __nv_bfloat162(h0, h1);
        *reinterpret_cast<__nv_bfloat162*>(&out_lo[r1o]) = __nv_bfloat162(lo0, lo1);
    }
}

// ---------------- launch ----------------
extern "C" void kernel_launch(void* const* d_in, const int* in_sizes, int n_in,
                              void* d_out, int out_size) {
    const float* x           = (const float*)d_in[0];
    const float* w_qkv       = (const float*)d_in[1];
    const float* w_attn_proj = (const float*)d_in[2];
    const float* w_fc        = (const float*)d_in[3];
    const float* w_mlp_proj  = (const float*)d_in[4];
    const float* ln1_w       = (const float*)d_in[5];
    const float* ln2_w       = (const float*)d_in[6];
    float* out = (float*)d_out;

    bf16 *p_h_hi, *p_h_lo, *p_attn_hi, *p_attn_lo, *p_fc_hi, *p_fc_lo;
    bf16 *p_wqkv_hi, *p_wqkv_lo, *p_wproj_hi, *p_wproj_lo;
    bf16 *p_wfc_hi, *p_wfc_lo, *p_wmlp_hi, *p_wmlp_lo;
    float *p_qkv, *p_x1;
    __half *p_kh, *p_kl, *p_vt;
    cudaGetSymbolAddress((void**)&p_h_hi, g_h_hi);
    cudaGetSymbolAddress((void**)&p_h_lo, g_h_lo);
    cudaGetSymbolAddress((void**)&p_qkv, g_qkv);
    cudaGetSymbolAddress((void**)&p_attn_hi, g_attn_hi);
    cudaGetSymbolAddress((void**)&p_attn_lo, g_attn_lo);
    cudaGetSymbolAddress((void**)&p_x1, g_x1);
    cudaGetSymbolAddress((void**)&p_fc_hi, g_fc_hi);
    cudaGetSymbolAddress((void**)&p_fc_lo, g_fc_lo);
    cudaGetSymbolAddress((void**)&p_wqkv_hi, g_wqkv_hi);
    cudaGetSymbolAddress((void**)&p_wqkv_lo, g_wqkv_lo);
    cudaGetSymbolAddress((void**)&p_wproj_hi, g_wproj_hi);
    cudaGetSymbolAddress((void**)&p_wproj_lo, g_wproj_lo);
    cudaGetSymbolAddress((void**)&p_wfc_hi, g_wfc_hi);
    cudaGetSymbolAddress((void**)&p_wfc_lo, g_wfc_lo);
    cudaGetSymbolAddress((void**)&p_wmlp_hi, g_wmlp_hi);
    cudaGetSymbolAddress((void**)&p_wmlp_lo, g_wmlp_lo);
    cudaGetSymbolAddress((void**)&p_kh, g_kh);
    cudaGetSymbolAddress((void**)&p_kl, g_kl);
    cudaGetSymbolAddress((void**)&p_vt, g_vt);

    const int gemm_smem = 2 * STAGE_ELEMS * (int)sizeof(bf16);          // 81,920 B
    cudaFuncSetAttribute(mma_gemm<0>, cudaFuncAttributeMaxDynamicSharedMemorySize, gemm_smem);
    cudaFuncSetAttribute(mma_gemm<1>, cudaFuncAttributeMaxDynamicSharedMemorySize, gemm_smem);
    cudaFuncSetAttribute(mma_gemm<2>, cudaFuncAttributeMaxDynamicSharedMemorySize, gemm_smem);
    const int flash_smem = (KVTILE + 2 * 3 * KVTILE) * (int)sizeof(__half);  // 64,512 B
    cudaFuncSetAttribute(flash2, cudaFuncAttributeMaxDynamicSharedMemorySize, flash_smem);

    // 0. weight transpose + split
    wt_split_kernel<<<dim3(C3 / 32, EMB / 32), 256>>>(w_qkv, p_wqkv_hi, p_wqkv_lo, EMB, C3);
    wt_split_kernel<<<dim3(EMB / 32, EMB / 32), 256>>>(w_attn_proj, p_wproj_hi, p_wproj_lo, EMB, EMB);
    wt_split_kernel<<<dim3(CFC / 32, EMB / 32), 256>>>(w_fc, p_wfc_hi, p_wfc_lo, EMB, CFC);
    wt_split_kernel<<<dim3(EMB / 32, CFC / 32), 256>>>(w_mlp_proj, p_wmlp_hi, p_wmlp_lo, CFC, EMB);

    // 1. h = LN(x, ln1)
    ln_kernel<<<SEQ, 256>>>(x, ln1_w, p_h_hi, p_h_lo);
    // 2. qkv = h @ w_qkv
    mma_gemm<0><<<dim3(C3 / 128, SEQ / 128), 128, gemm_smem>>>(
        p_h_hi, p_h_lo, p_wqkv_hi, p_wqkv_lo, nullptr, p_qkv, nullptr, nullptr, SEQ, C3, EMB);
    // 3a. K/V fp16 prep
    kv_prep<<<dim3(SEQ / 64, NHEAD), 256>>>(p_qkv, p_kh, p_kl, p_vt);
    // 3b. attention (FA2, register-resident)
    flash2<<<dim3(SEQ / 64, NHEAD), 128, flash_smem>>>(p_qkv, p_kh, p_kl, p_vt, p_attn_hi, p_attn_lo);
    // 4. x1 = x + attn @ w_attn_proj
    mma_gemm<1><<<dim3(EMB / 128, SEQ / 128), 128, gemm_smem>>>(
        p_attn_hi, p_attn_lo, p_wproj_hi, p_wproj_lo, x, p_x1, nullptr, nullptr, SEQ, EMB, EMB);
    // 5. h = LN(x1, ln2)
    ln_kernel<<<SEQ, 256>>>(p_x1, ln2_w, p_h_hi, p_h_lo);
    // 6. fc = gelu(h @ w_fc)  (register epilogue)
    mma_gemm<2><<<dim3(CFC / 128, SEQ / 128), 128, gemm_smem>>>(
        p_h_hi, p_h_lo, p_wfc_hi, p_wfc_lo, nullptr, nullptr, p_fc_hi, p_fc_lo, SEQ, CFC, EMB);
    // 7. out = x1 + fc @ w_mlp_proj
    mma_gemm<1><<<dim3(EMB / 128, SEQ / 128), 128, gemm_smem>>>(
        p_fc_hi, p_fc_lo, p_wmlp_hi, p_wmlp_lo, p_x1, out, nullptr, nullptr, SEQ, EMB, CFC);
}

// round 8
// speedup vs baseline: 1.8032x; 1.2598x over previous
#include <cuda_runtime.h>
#include <cuda_bf16.h>
#include <cuda_fp16.h>
#include <cstdint>
#include <math.h>

// Block: B=1, T=4096, C=1024, H=16, hs=64
#define SEQ 4096
#define EMB 1024
#define NHEAD 16
#define HS 64
#define C3 3072
#define CFC 4096

typedef __nv_bfloat16 bf16;

// ---------------- device scratch (no allocations allowed) ----------------
__device__ __half g_h_hi[SEQ * EMB], g_h_lo[SEQ * EMB];        // LN out (fp16 split)
__device__ float g_qkv[SEQ * C3];                              // qkv fp32
__device__ __half g_attn_hi[SEQ * EMB], g_attn_lo[SEQ * EMB];  // attention out (fp16 split)
__device__ float g_x1[SEQ * EMB];                              // x + attn_proj
__device__ __half g_fc_hi[SEQ * CFC], g_fc_lo[SEQ * CFC];      // gelu(fc) (fp16 split)
// transposed fp16 weights: Wt[n][k]
__device__ __half g_wqkv[C3 * EMB];
__device__ __half g_wproj[EMB * EMB];
__device__ __half g_wfc[CFC * EMB];
__device__ __half g_wmlp[EMB * CFC];
// fp16 K (hi/lo) per head [hd][seq][64]; V transposed per head [hd][d][seq]
__device__ __half g_kh[NHEAD * SEQ * HS], g_kl[NHEAD * SEQ * HS];
__device__ __half g_vt[NHEAD * HS * SEQ];

__device__ __forceinline__ void split_h(float v, __half& hi, __half& lo) {
    hi = __float2half(v);
    lo = __float2half(v - __half2float(hi));
}
__device__ __forceinline__ float gelu_exact(float v) {
    return 0.5f * v * (1.0f + erff(v * 0.70710678118654752440f));
}

// ---- smem/cp.async/mma helpers ----
__device__ __forceinline__ uint32_t smem_u32(const void* p) {
    uint32_t a;
    asm("{ .reg .u64 t; cvta.to.shared.u64 t, %1; cvt.u32.u64 %0, t; }" : "=r"(a) : "l"(p));
    return a;
}
__device__ __forceinline__ void cp16(void* sp, const void* gp) {
    asm volatile("cp.async.cg.shared.global [%0], [%1], 16;" :: "r"(smem_u32(sp)), "l"(gp));
}
__device__ __forceinline__ void cp_commit() {
    asm volatile("cp.async.commit_group;" ::: "memory");
}
__device__ __forceinline__ void cp_wait0() {
    asm volatile("cp.async.wait_group 0;" ::: "memory");
}
__device__ __forceinline__ void cp_wait1() {
    asm volatile("cp.async.wait_group 1;" ::: "memory");
}
__device__ __forceinline__ void ldsm4(uint32_t* r, uint32_t addr) {
    asm volatile("ldmatrix.sync.aligned.m8n8.x4.shared.b16 {%0,%1,%2,%3}, [%4];"
                 : "=r"(r[0]), "=r"(r[1]), "=r"(r[2]), "=r"(r[3]) : "r"(addr));
}
__device__ __forceinline__ void mma16816(float* c, const uint32_t* a, uint32_t b0, uint32_t b1) {
    asm volatile(
        "mma.sync.aligned.m16n8k16.row.col.f32.f16.f16.f32 "
        "{%0,%1,%2,%3}, {%4,%5,%6,%7}, {%8,%9}, {%0,%1,%2,%3};"
        : "+f"(c[0]), "+f"(c[1]), "+f"(c[2]), "+f"(c[3])
        : "r"(a[0]), "r"(a[1]), "r"(a[2]), "r"(a[3]), "r"(b0), "r"(b1));
}
__device__ __forceinline__ uint32_t pack_h2(float x, float y) {
    __half2 h = __floats2half2_rn(x, y);
    return *reinterpret_cast<uint32_t*>(&h);
}

// ---------------- LayerNorm -> split fp16 ----------------
__global__ void ln_kernel(const float* __restrict__ x, const float* __restrict__ w,
                          __half* __restrict__ out_hi, __half* __restrict__ out_lo) {
    const int row = blockIdx.x;
    const int tid = threadIdx.x;  // 256, 4 floats each
    const float4 v = reinterpret_cast<const float4*>(x + (size_t)row * EMB)[tid];

    float s = v.x + v.y + v.z + v.w;
    float q = v.x * v.x + v.y * v.y + v.z * v.z + v.w * v.w;
    #pragma unroll
    for (int off = 16; off > 0; off >>= 1) {
        s += __shfl_xor_sync(0xffffffffu, s, off);
        q += __shfl_xor_sync(0xffffffffu, q, off);
    }
    __shared__ float ws[8], wq[8], s_mean, s_rstd;
    const int wid = tid >> 5, lane = tid & 31;
    if (lane == 0) { ws[wid] = s; wq[wid] = q; }
    __syncthreads();
    if (tid == 0) {
        float S = 0.f, Q = 0.f;
        #pragma unroll
        for (int i = 0; i < 8; i++) { S += ws[i]; Q += wq[i]; }
        float mean = S * (1.0f / EMB);
        float var = Q * (1.0f / EMB) - mean * mean;
        s_mean = mean;
        s_rstd = rsqrtf(var + 1e-5f);
    }
    __syncthreads();
    const float mean = s_mean, rstd = s_rstd;
    const float4 g = reinterpret_cast<const float4*>(w)[tid];
    float o[4] = {(v.x - mean) * rstd * g.x, (v.y - mean) * rstd * g.y,
                  (v.z - mean) * rstd * g.z, (v.w - mean) * rstd * g.w};
    const size_t base = (size_t)row * EMB + tid * 4;
    #pragma unroll
    for (int i = 0; i < 4; i++) {
        __half hi, lo;
        split_h(o[i], hi, lo);
        out_hi[base + i] = hi;
        out_lo[base + i] = lo;
    }
}

// ---------------- weight transpose: W[K,N] fp32 -> Wt[N,K] fp16 ----------------
__global__ __launch_bounds__(256) void wt_kernel(const float* __restrict__ W,
                                                 __half* __restrict__ tw,
                                                 int K, int N) {
    __shared__ float tile[32][33];
    const int bn = blockIdx.x * 32;
    const int bk = blockIdx.y * 32;
    const int tx = threadIdx.x & 31, ty = threadIdx.x >> 5;
    #pragma unroll
    for (int r = ty; r < 32; r += 8)
        tile[r][tx] = W[(size_t)(bk + r) * N + bn + tx];
    __syncthreads();
    #pragma unroll
    for (int r = ty; r < 32; r += 8)
        tw[(size_t)(bn + r) * K + bk + tx] = __float2half(tile[tx][r]);
}

// ---------------- K/V fp16 prep: split K, transpose V ----------------
__global__ __launch_bounds__(256) void kv_prep(const float* __restrict__ qkv,
                                               __half* __restrict__ kh,
                                               __half* __restrict__ kl,
                                               __half* __restrict__ vt) {
    __shared__ __half vts[64][65];
    const int sb = blockIdx.x, hd = blockIdx.y;
    const int tid = threadIdx.x;
    for (int i = tid; i < 4096; i += 256) {
        const int r = i >> 6, c = i & 63;
        const size_t base = (size_t)(sb * 64 + r) * C3 + hd * HS;
        const float k = qkv[base + EMB + c];
        const __half h = __float2half(k);
        const size_t ko = ((size_t)hd * SEQ + sb * 64 + r) * HS + c;
        kh[ko] = h;
        kl[ko] = __float2half(k - __half2float(h));
        vts[c][r] = __float2half(qkv[base + 2 * EMB + c]);
    }
    __syncthreads();
    for (int i = tid; i < 4096; i += 256) {
        const int d = i >> 6, ss = i & 63;
        vt[((size_t)hd * HS + d) * SEQ + sb * 64 + ss] = vts[d][ss];
    }
}

// ---------------- raw-MMA GEMM: fp16 2-pass (A hi/lo, B single fp16) ----------------
// 128x128 CTA (4 warps, 64x64 warp tile), KC=32.
// C[M,N] = A[M,K] @ Wt[N,K]^T.  EPI: 0 = fp32 C, 1 = C = R + acc, 2 = gelu(acc)->split fp16
#define KC2 32
#define SPAD 40                         // conflict-free ldmatrix (80B row stride)
#define SLAB (128 * SPAD)
#define STAGE_ELEMS (3 * SLAB)          // Ah, Al, Bf

template <int EPI>
__global__ __launch_bounds__(128, 2) void mma_gemm(
    const __half* __restrict__ Ah, const __half* __restrict__ Al,
    const __half* __restrict__ Bf,
    const float* __restrict__ R, float* __restrict__ C,
    __half* __restrict__ Chi, __half* __restrict__ Clo,
    int M, int N, int K) {
    extern __shared__ char smraw[];
    __half* sm = reinterpret_cast<__half*>(smraw);
    const uint32_t smb = smem_u32(sm);

    const int tid = threadIdx.x;
    const int warp = tid >> 5, lane = tid & 31;
    const int wm = warp & 1;        // 2 warps in M (64 rows)
    const int wn = warp >> 1;       // 2 warps in N (64 cols)
    const int gid = lane >> 2, tig = lane & 3;
    const int bm = blockIdx.y * 128, bn = blockIdx.x * 128;

    float acc[4][8][4];
    if (EPI == 1) {
        #pragma unroll
        for (int mt = 0; mt < 4; mt++) {
            const size_t r0 = (size_t)(bm + wm * 64 + mt * 16 + gid) * N;
            const size_t r1 = r0 + 8 * N;
            #pragma unroll
            for (int nt = 0; nt < 8; nt++) {
                const int col = bn + wn * 64 + nt * 8 + tig * 2;
                const float2 v0 = *reinterpret_cast<const float2*>(R + r0 + col);
                const float2 v1 = *reinterpret_cast<const float2*>(R + r1 + col);
                acc[mt][nt][0] = v0.x; acc[mt][nt][1] = v0.y;
                acc[mt][nt][2] = v1.x; acc[mt][nt][3] = v1.y;
            }
        }
    } else {
        #pragma unroll
        for (int mt = 0; mt < 4; mt++)
            #pragma unroll
            for (int nt = 0; nt < 8; nt++)
                #pragma unroll
                for (int t = 0; t < 4; t++) acc[mt][nt][t] = 0.f;
    }

    const int NC = K / KC2;

    // stage loader: 3 slabs x 128 rows x 32 cols (4 cp16/row-slab) -> 12 cp16/thread
    auto load_stage = [&](int buf, int k0) {
        __half* st = sm + buf * STAGE_ELEMS;
        #pragma unroll
        for (int o = 0; o < 4; o++) {
            const int idx = tid + o * 128;       // 0..511
            const int row = idx >> 2, seg = idx & 3;
            const int soff = row * SPAD + seg * 8;
            const size_t ga = (size_t)(bm + row) * K + k0 + seg * 8;
            const size_t gb = (size_t)(bn + row) * K + k0 + seg * 8;
            cp16(st + soff,            Ah + ga);
            cp16(st + SLAB + soff,     Al + ga);
            cp16(st + 2 * SLAB + soff, Bf + gb);
        }
    };

    const int a_row = wm * 64 + (lane & 15);
    const int a_col = (lane >> 4) << 3;
    const int b_row = wn * 64 + (lane & 7) + ((lane >> 4) << 3);
    const int b_col = ((lane >> 3) & 1) << 3;

    load_stage(0, 0);
    cp_commit();

    for (int c = 0; c < NC; c++) {
        if (c + 1 < NC) {
            load_stage((c + 1) & 1, (c + 1) * KC2);
            cp_commit();
            cp_wait1();
        } else {
            cp_wait0();
        }
        __syncthreads();

        const uint32_t st = smb + (c & 1) * STAGE_ELEMS * 2;  // bytes
        const uint32_t sAh = st;
        const uint32_t sAl = st + SLAB * 2;
        const uint32_t sBf = st + 2 * SLAB * 2;

        #pragma unroll
        for (int kk = 0; kk < KC2 / 16; kk++) {
            uint32_t bh[8][2];
            #pragma unroll
            for (int p = 0; p < 4; p++) {
                const uint32_t boff = ((b_row + p * 16) * SPAD + kk * 16 + b_col) * 2;
                uint32_t t4[4];
                ldsm4(t4, sBf + boff);
                bh[2 * p][0] = t4[0]; bh[2 * p][1] = t4[1];
                bh[2 * p + 1][0] = t4[2]; bh[2 * p + 1][1] = t4[3];
            }
            #pragma unroll
            for (int mt = 0; mt < 4; mt++) {
                const uint32_t aoff = ((a_row + mt * 16) * SPAD + kk * 16 + a_col) * 2;
                uint32_t ah[4], al[4];
                ldsm4(ah, sAh + aoff);
                ldsm4(al, sAl + aoff);
                #pragma unroll
                for (int nt = 0; nt < 8; nt++) {
                    mma16816(acc[mt][nt], ah, bh[nt][0], bh[nt][1]);
                    mma16816(acc[mt][nt], al, bh[nt][0], bh[nt][1]);
                }
            }
        }
        __syncthreads();
    }

    // ---- register epilogue ----
    #pragma unroll
    for (int mt = 0; mt < 4; mt++) {
        const size_t r0 = (size_t)(bm + wm * 64 + mt * 16 + gid) * N;
        const size_t r1 = r0 + 8 * N;
        #pragma unroll
        for (int nt = 0; nt < 8; nt++) {
            const int col = bn + wn * 64 + nt * 8 + tig * 2;
            if (EPI != 2) {
                *reinterpret_cast<float2*>(C + r0 + col) =
                    make_float2(acc[mt][nt][0], acc[mt][nt][1]);
                *reinterpret_cast<float2*>(C + r1 + col) =
                    make_float2(acc[mt][nt][2], acc[mt][nt][3]);
            } else {
                __half h0, l0, h1, l1;
                split_h(gelu_exact(acc[mt][nt][0]), h0, l0);
                split_h(gelu_exact(acc[mt][nt][1]), h1, l1);
                *reinterpret_cast<__half2*>(&Chi[r0 + col]) = __half2(h0, h1);
                *reinterpret_cast<__half2*>(&Clo[r0 + col]) = __half2(l0, l1);
                split_h(gelu_exact(acc[mt][nt][2]), h0, l0);
                split_h(gelu_exact(acc[mt][nt][3]), h1, l1);
                *reinterpret_cast<__half2*>(&Chi[r1 + col]) = __half2(h0, h1);
                *reinterpret_cast<__half2*>(&Clo[r1 + col]) = __half2(l0, l1);
            }
        }
    }
}

// ---------------- FA2 flash attention: register-resident, mma.sync ----------------
#define KVPAD 72
#define KVTILE (64 * KVPAD)

__global__ __launch_bounds__(128) void flash2(
    const float* __restrict__ qkv,
    const __half* __restrict__ kh, const __half* __restrict__ kl,
    const __half* __restrict__ vt,
    __half* __restrict__ out_hi, __half* __restrict__ out_lo) {
    extern __shared__ char smraw[];
    __half* Qs = reinterpret_cast<__half*>(smraw);   // 64 x 72
    __half* KB = Qs + KVTILE;                        // [2 buf][Kh,Kl,Vt][64 x 72]

    const int tid = threadIdx.x;
    const int warp = tid >> 5, lane = tid & 31;
    const int gid = lane >> 2, tig = lane & 3;
    const int qb = (int)gridDim.x - 1 - (int)blockIdx.x;   // heavy tiles first
    const int hd = blockIdx.y;

    for (int i = tid; i < 4096; i += 128) {
        const int r = i >> 6, c = i & 63;
        Qs[r * KVPAD + c] =
            __float2half(qkv[(size_t)(qb * 64 + r) * C3 + hd * HS + c] * 0.125f);
    }
    __syncthreads();

    uint32_t qa[4][4];
    const int row0 = warp * 16 + gid;
    #pragma unroll
    for (int kk = 0; kk < 4; kk++) {
        qa[kk][0] = *reinterpret_cast<const uint32_t*>(&Qs[row0 * KVPAD + kk * 16 + tig * 2]);
        qa[kk][1] = *reinterpret_cast<const uint32_t*>(&Qs[(row0 + 8) * KVPAD + kk * 16 + tig * 2]);
        qa[kk][2] = *reinterpret_cast<const uint32_t*>(&Qs[row0 * KVPAD + kk * 16 + 8 + tig * 2]);
        qa[kk][3] = *reinterpret_cast<const uint32_t*>(&Qs[(row0 + 8) * KVPAD + kk * 16 + 8 + tig * 2]);
    }

    float o[8][4];
    #pragma unroll
    for (int j = 0; j < 8; j++)
        #pragma unroll
        for (int t = 0; t < 4; t++) o[j][t] = 0.f;
    float m0 = -1e30f, m1 = -1e30f, l0 = 0.f, l1 = 0.f;

    const size_t khb = (size_t)hd * SEQ * HS;
    const size_t vtb = (size_t)hd * HS * SEQ;

    auto prefetch = [&](int buf, int kt) {
        __half* st = KB + buf * (3 * KVTILE);
        #pragma unroll
        for (int o2 = 0; o2 < 4; o2++) {
            const int idx = tid + o2 * 128;
            const int r = idx >> 3, seg = idx & 7;
            const int so = r * KVPAD + seg * 8;
            cp16(st + so,               kh + khb + (size_t)(kt * 64 + r) * HS + seg * 8);
            cp16(st + KVTILE + so,      kl + khb + (size_t)(kt * 64 + r) * HS + seg * 8);
            cp16(st + 2 * KVTILE + so,  vt + vtb + (size_t)r * SEQ + kt * 64 + seg * 8);
        }
    };

    prefetch(0, 0);
    cp_commit();

    for (int kt = 0; kt <= qb; kt++) {
        if (kt < qb) {
            prefetch((kt + 1) & 1, kt + 1);
            cp_commit();
            cp_wait1();
        } else {
            cp_wait0();
        }
        __syncthreads();

        __half* st = KB + (kt & 1) * (3 * KVTILE);
        const __half* Kh = st;
        const __half* Kl = st + KVTILE;
        const __half* Vt = st + 2 * KVTILE;

        float s[8][4];
        #pragma unroll
        for (int j = 0; j < 8; j++)
            #pragma unroll
            for (int t = 0; t < 4; t++) s[j][t] = 0.f;
        #pragma unroll
        for (int kk = 0; kk < 4; kk++)
            #pragma unroll
            for (int j = 0; j < 8; j++) {
                const int off = (j * 8 + gid) * KVPAD + kk * 16 + tig * 2;
                uint32_t b0 = *reinterpret_cast<const uint32_t*>(&Kh[off]);
                uint32_t b1 = *reinterpret_cast<const uint32_t*>(&Kh[off + 8]);
                mma16816(s[j], qa[kk], b0, b1);
                b0 = *reinterpret_cast<const uint32_t*>(&Kl[off]);
                b1 = *reinterpret_cast<const uint32_t*>(&Kl[off + 8]);
                mma16816(s[j], qa[kk], b0, b1);
            }

        if (kt == qb) {
            #pragma unroll
            for (int j = 0; j < 8; j++) {
                const int c0 = j * 8 + tig * 2;
                if (c0 > row0)         s[j][0] = -1e30f;
                if (c0 + 1 > row0)     s[j][1] = -1e30f;
                if (c0 > row0 + 8)     s[j][2] = -1e30f;
                if (c0 + 1 > row0 + 8) s[j][3] = -1e30f;
            }
        }

        float mx0 = -1e30f, mx1 = -1e30f;
        #pragma unroll
        for (int j = 0; j < 8; j++) {
            mx0 = fmaxf(mx0, fmaxf(s[j][0], s[j][1]));
            mx1 = fmaxf(mx1, fmaxf(s[j][2], s[j][3]));
        }
        mx0 = fmaxf(mx0, __shfl_xor_sync(0xffffffffu, mx0, 1));
        mx0 = fmaxf(mx0, __shfl_xor_sync(0xffffffffu, mx0, 2));
        mx1 = fmaxf(mx1, __shfl_xor_sync(0xffffffffu, mx1, 1));
        mx1 = fmaxf(mx1, __shfl_xor_sync(0xffffffffu, mx1, 2));
        const float mn0 = fmaxf(m0, mx0), mn1 = fmaxf(m1, mx1);
        const float al0 = __expf(m0 - mn0), al1 = __expf(m1 - mn1);
        float rs0 = 0.f, rs1 = 0.f;
        #pragma unroll
        for (int j = 0; j < 8; j++) {
            s[j][0] = __expf(s[j][0] - mn0);
            s[j][1] = __expf(s[j][1] - mn0);
            s[j][2] = __expf(s[j][2] - mn1);
            s[j][3] = __expf(s[j][3] - mn1);
            rs0 += s[j][0] + s[j][1];
            rs1 += s[j][2] + s[j][3];
        }
        rs0 += __shfl_xor_sync(0xffffffffu, rs0, 1);
        rs0 += __shfl_xor_sync(0xffffffffu, rs0, 2);
        rs1 += __shfl_xor_sync(0xffffffffu, rs1, 1);
        rs1 += __shfl_xor_sync(0xffffffffu, rs1, 2);
        l0 = l0 * al0 + rs0;
        l1 = l1 * al1 + rs1;
        m0 = mn0;
        m1 = mn1;
        #pragma unroll
        for (int j = 0; j < 8; j++) {
            o[j][0] *= al0; o[j][1] *= al0;
            o[j][2] *= al1; o[j][3] *= al1;
        }

        #pragma unroll
        for (int kk = 0; kk < 4; kk++) {
            uint32_t pa[4];
            pa[0] = pack_h2(s[2 * kk][0], s[2 * kk][1]);
            pa[1] = pack_h2(s[2 * kk][2], s[2 * kk][3]);
            pa[2] = pack_h2(s[2 * kk + 1][0], s[2 * kk + 1][1]);
            pa[3] = pack_h2(s[2 * kk + 1][2], s[2 * kk + 1][3]);
            #pragma unroll
            for (int j = 0; j < 8; j++) {
                const int off = (j * 8 + gid) * KVPAD + kk * 16 + tig * 2;
                const uint32_t b0 = *reinterpret_cast<const uint32_t*>(&Vt[off]);
                const uint32_t b1 = *reinterpret_cast<const uint32_t*>(&Vt[off + 8]);
                mma16816(o[j], pa, b0, b1);
            }
        }
        __syncthreads();
    }

    const float inv0 = 1.0f / l0, inv1 = 1.0f / l1;
    #pragma unroll
    for (int j = 0; j < 8; j++) {
        const int d = hd * HS + j * 8 + tig * 2;
        const size_t r0o = (size_t)(qb * 64 + row0) * EMB + d;
        const size_t r1o = (size_t)(qb * 64 + row0 + 8) * EMB + d;
        __half h0, lo0, h1, lo1;
        split_h(o[j][0] * inv0, h0, lo0);
        split_h(o[j][1] * inv0, h1, lo1);
        *reinterpret_cast<__half2*>(&out_hi[r0o]) = __half2(h0, h1);
        *reinterpret_cast<__half2*>(&out_lo[r0o]) = __half2(lo0, lo1);
        split_h(o[j][2] * inv1, h0, lo0);
        split_h(o[j][3] * inv1, h1, lo1);
        *reinterpret_cast<__half2*>(&out_hi[r1o]) = __half2(h0, h1);
        *reinterpret_cast<__half2*>(&out_lo[r1o]) = __half2(lo0, lo1);
    }
}

// ---------------- launch ----------------
extern "C" void kernel_launch(void* const* d_in, const int* in_sizes, int n_in,
                              void* d_out, int out_size) {
    const float* x           = (const float*)d_in[0];
    const float* w_qkv       = (const float*)d_in[1];
    const float* w_attn_proj = (const float*)d_in[2];
    const float* w_fc        = (const float*)d_in[3];
    const float* w_mlp_proj  = (const float*)d_in[4];
    const float* ln1_w       = (const float*)d_in[5];
    const float* ln2_w       = (const float*)d_in[6];
    float* out = (float*)d_out;

    __half *p_h_hi, *p_h_lo, *p_attn_hi, *p_attn_lo, *p_fc_hi, *p_fc_lo;
    __half *p_wqkv, *p_wproj, *p_wfc, *p_wmlp;
    float *p_qkv, *p_x1;
    __half *p_kh, *p_kl, *p_vt;
    cudaGetSymbolAddress((void**)&p_h_hi, g_h_hi);
    cudaGetSymbolAddress((void**)&p_h_lo, g_h_lo);
    cudaGetSymbolAddress((void**)&p_qkv, g_qkv);
    cudaGetSymbolAddress((void**)&p_attn_hi, g_attn_hi);
    cudaGetSymbolAddress((void**)&p_attn_lo, g_attn_lo);
    cudaGetSymbolAddress((void**)&p_x1, g_x1);
    cudaGetSymbolAddress((void**)&p_fc_hi, g_fc_hi);
    cudaGetSymbolAddress((void**)&p_fc_lo, g_fc_lo);
    cudaGetSymbolAddress((void**)&p_wqkv, g_wqkv);
    cudaGetSymbolAddress((void**)&p_wproj, g_wproj);
    cudaGetSymbolAddress((void**)&p_wfc, g_wfc);
    cudaGetSymbolAddress((void**)&p_wmlp, g_wmlp);
    cudaGetSymbolAddress((void**)&p_kh, g_kh);
    cudaGetSymbolAddress((void**)&p_kl, g_kl);
    cudaGetSymbolAddress((void**)&p_vt, g_vt);

    const int gemm_smem = 2 * STAGE_ELEMS * (int)sizeof(__half);        // 61,440 B
    cudaFuncSetAttribute(mma_gemm<0>, cudaFuncAttributeMaxDynamicSharedMemorySize, gemm_smem);
    cudaFuncSetAttribute(mma_gemm<1>, cudaFuncAttributeMaxDynamicSharedMemorySize, gemm_smem);
    cudaFuncSetAttribute(mma_gemm<2>, cudaFuncAttributeMaxDynamicSharedMemorySize, gemm_smem);
    const int flash_smem = (KVTILE + 2 * 3 * KVTILE) * (int)sizeof(__half);  // 64,512 B
    cudaFuncSetAttribute(flash2, cudaFuncAttributeMaxDynamicSharedMemorySize, flash_smem);

    // launch order puts mma_gemm<0> at slot 5 so ncu (-s 5 -c 1) profiles it
    // 0. h = LN(x, ln1)
    ln_kernel<<<SEQ, 256>>>(x, ln1_w, p_h_hi, p_h_lo);
    // 1-4. weight transpose to fp16
    wt_kernel<<<dim3(C3 / 32, EMB / 32), 256>>>(w_qkv, p_wqkv, EMB, C3);
    wt_kernel<<<dim3(EMB / 32, EMB / 32), 256>>>(w_attn_proj, p_wproj, EMB, EMB);
    wt_kernel<<<dim3(CFC / 32, EMB / 32), 256>>>(w_fc, p_wfc, EMB, CFC);
    wt_kernel<<<dim3(EMB / 32, CFC / 32), 256>>>(w_mlp_proj, p_wmlp, CFC, EMB);
    // 5. qkv = h @ w_qkv
    mma_gemm<0><<<dim3(C3 / 128, SEQ / 128), 128, gemm_smem>>>(
        p_h_hi, p_h_lo, p_wqkv, nullptr, p_qkv, nullptr, nullptr, SEQ, C3, EMB);
    // 6. K/V fp16 prep
    kv_prep<<<dim3(SEQ / 64, NHEAD), 256>>>(p_qkv, p_kh, p_kl, p_vt);
    // 7. attention (FA2, register-resident)
    flash2<<<dim3(SEQ / 64, NHEAD), 128, flash_smem>>>(p_qkv, p_kh, p_kl, p_vt, p_attn_hi, p_attn_lo);
    // 8. x1 = x + attn @ w_attn_proj
    mma_gemm<1><<<dim3(EMB / 128, SEQ / 128), 128, gemm_smem>>>(
        p_attn_hi, p_attn_lo, p_wproj, x, p_x1, nullptr, nullptr, SEQ, EMB, EMB);
    // 9. h = LN(x1, ln2)
    ln_kernel<<<SEQ, 256>>>(p_x1, ln2_w, p_h_hi, p_h_lo);
    // 10. fc = gelu(h @ w_fc)  (register epilogue)
    mma_gemm<2><<<dim3(CFC / 128, SEQ / 128), 128, gemm_smem>>>(
        p_h_hi, p_h_lo, p_wfc, nullptr, nullptr, p_fc_hi, p_fc_lo, SEQ, CFC, EMB);
    // 11. out = x1 + fc @ w_mlp_proj
    mma_gemm<1><<<dim3(EMB / 128, SEQ / 128), 128, gemm_smem>>>(
        p_fc_hi, p_fc_lo, p_wmlp, p_x1, out, nullptr, nullptr, SEQ, EMB, CFC);
}